// round 2
// baseline (speedup 1.0000x reference)
#include <cuda_runtime.h>
#include <cuda_bf16.h>
#include <cstdint>

#define Bc   16
#define NFc  16
#define Nc   1024
#define Dc   128
#define Sc   8
#define Hc   128
#define BSc  (Bc*Sc)          // 128
#define SCALEc 0.08838834764831845f
#define EPSc   1e-8f

// ---------------- device scratch (no allocations allowed) ----------------
__device__ float g_K[Bc*NFc*Nc*Dc];     // 134 MB
__device__ float g_V[Bc*NFc*Nc*Dc];     // 134 MB
__device__ float g_q[BSc*Dc];
__device__ float g_slots[BSc*Dc];
__device__ float g_Upart[8*BSc*Dc];     // per 128-token chunk partial updates
__device__ float g_rspart[8*BSc];       // per chunk partial rowsums
__device__ float g_WqT[Dc*Dc];
__device__ float g_W1T[Dc*Hc];
__device__ float g_W2T[Hc*Dc];
__device__ float g_WihT[Dc*3*Dc];
__device__ float g_WhhT[Dc*3*Dc];

// ---------------- helpers ----------------
__device__ __forceinline__ float blocksum128(float v, float* red) {
    #pragma unroll
    for (int o = 16; o; o >>= 1) v += __shfl_xor_sync(0xffffffffu, v, o);
    int t = threadIdx.x;
    if ((t & 31) == 0) red[t >> 5] = v;
    __syncthreads();
    float r = red[0] + red[1] + red[2] + red[3];
    __syncthreads();
    return r;
}

__device__ __forceinline__ float sigmoidf_(float x) { return 1.0f / (1.0f + expf(-x)); }

// ---------------- weight transposes (coalesced GEMV access later) --------
__global__ void prep_kernel(const float* __restrict__ Wq, const float* __restrict__ W1,
                            const float* __restrict__ W2, const float* __restrict__ Wih,
                            const float* __restrict__ Whh) {
    int idx = blockIdx.x * 256 + threadIdx.x;
    if (idx < Dc * Dc) {
        int r = idx >> 7, c = idx & 127;
        g_WqT[c * Dc + r] = Wq[idx];
        g_W1T[c * Dc + r] = W1[idx];
        g_W2T[c * Dc + r] = W2[idx];
    }
    if (idx < 3 * Dc * Dc) {
        int j = idx >> 7, d = idx & 127;
        g_WihT[d * 384 + j] = Wih[idx];
        g_WhhT[d * 384 + j] = Whh[idx];
    }
}

// ---------------- K0: LN(x) then K,V projections for all (b,f) ----------
// grid: (N/32, B*NF), 128 threads. smem: wk[128*132] + wv[128*132] + xs[32*132]
#define WST 132
#define K0_SMEM ((2*128*WST + 32*WST) * 4)
__global__ void k0_kernel(const float* __restrict__ x,
                          const float* __restrict__ Wk, const float* __restrict__ bk,
                          const float* __restrict__ Wv, const float* __restrict__ bv,
                          const float* __restrict__ g_in, const float* __restrict__ be_in) {
    extern __shared__ float sm[];
    float* wk = sm;
    float* wv = wk + 128 * WST;
    float* xs = wv + 128 * WST;
    const int t = threadIdx.x;
    const int bf = blockIdx.y;
    const int rowbase = blockIdx.x * 32;

    // weights into smem, d-major: wsm[d*WST + c] = W[c*128 + d]
    for (int idx = t; idx < Dc * Dc; idx += 128) {
        int c = idx >> 7, d = idx & 127;
        wk[d * WST + c] = Wk[idx];
        wv[d * WST + c] = Wv[idx];
    }

    // LayerNorm of 32 rows into xs (row-major, stride WST)
    const int warp = t >> 5, lane = t & 31;
    float4 gg = ((const float4*)g_in)[lane];
    float4 bb = ((const float4*)be_in)[lane];
    const float* xbase = x + (size_t)bf * Nc * Dc + (size_t)rowbase * Dc;
    for (int r = warp; r < 32; r += 4) {
        float4 v = ((const float4*)(xbase + r * Dc))[lane];
        float s = v.x + v.y + v.z + v.w;
        #pragma unroll
        for (int o = 16; o; o >>= 1) s += __shfl_xor_sync(0xffffffffu, s, o);
        float m = s * (1.0f / 128.0f);
        float dx0 = v.x - m, dx1 = v.y - m, dx2 = v.z - m, dx3 = v.w - m;
        float ss = dx0 * dx0 + dx1 * dx1 + dx2 * dx2 + dx3 * dx3;
        #pragma unroll
        for (int o = 16; o; o >>= 1) ss += __shfl_xor_sync(0xffffffffu, ss, o);
        float inv = rsqrtf(ss * (1.0f / 128.0f) + 1e-5f);
        float* xr = xs + r * WST + lane * 4;
        xr[0] = dx0 * inv * gg.x + bb.x;
        xr[1] = dx1 * inv * gg.y + bb.y;
        xr[2] = dx2 * inv * gg.z + bb.z;
        xr[3] = dx3 * inv * gg.w + bb.w;
    }
    __syncthreads();

    const int c0 = (t & 31) * 4;
    const int r0 = (t >> 5) * 8;
    const size_t obase = (size_t)bf * Nc * Dc + (size_t)(rowbase + r0) * Dc + c0;

    // K
    {
        float acc[8][4];
        #pragma unroll
        for (int i = 0; i < 8; i++) { acc[i][0]=0; acc[i][1]=0; acc[i][2]=0; acc[i][3]=0; }
        #pragma unroll 4
        for (int d = 0; d < 128; d++) {
            float4 w = *(float4*)&wk[d * WST + c0];
            #pragma unroll
            for (int i = 0; i < 8; i++) {
                float xv = xs[(r0 + i) * WST + d];
                acc[i][0] += xv * w.x; acc[i][1] += xv * w.y;
                acc[i][2] += xv * w.z; acc[i][3] += xv * w.w;
            }
        }
        float4 b4 = *(const float4*)&bk[c0];
        #pragma unroll
        for (int i = 0; i < 8; i++) {
            float4 o = make_float4(acc[i][0]+b4.x, acc[i][1]+b4.y, acc[i][2]+b4.z, acc[i][3]+b4.w);
            *(float4*)(g_K + obase + (size_t)i * Dc) = o;
        }
    }
    // V
    {
        float acc[8][4];
        #pragma unroll
        for (int i = 0; i < 8; i++) { acc[i][0]=0; acc[i][1]=0; acc[i][2]=0; acc[i][3]=0; }
        #pragma unroll 4
        for (int d = 0; d < 128; d++) {
            float4 w = *(float4*)&wv[d * WST + c0];
            #pragma unroll
            for (int i = 0; i < 8; i++) {
                float xv = xs[(r0 + i) * WST + d];
                acc[i][0] += xv * w.x; acc[i][1] += xv * w.y;
                acc[i][2] += xv * w.z; acc[i][3] += xv * w.w;
            }
        }
        float4 b4 = *(const float4*)&bv[c0];
        #pragma unroll
        for (int i = 0; i < 8; i++) {
            float4 o = make_float4(acc[i][0]+b4.x, acc[i][1]+b4.y, acc[i][2]+b4.z, acc[i][3]+b4.w);
            *(float4*)(g_V + obase + (size_t)i * Dc) = o;
        }
    }
}

// ---------------- init: slots = broadcast(slots_init); q0 ----------------
__global__ void init_kernel(const float* __restrict__ slots_init,
                            const float* __restrict__ g_sl, const float* __restrict__ be_sl,
                            const float* __restrict__ bq) {
    __shared__ float lnv[Dc];
    __shared__ float red[4];
    const int t = threadIdx.x;
    const int bs = blockIdx.x;           // b*8 + s
    const int s = bs & 7;
    float v = slots_init[s * Dc + t];
    g_slots[bs * Dc + t] = v;
    float m = blocksum128(v, red) * (1.0f / 128.0f);
    float dx = v - m;
    float var = blocksum128(dx * dx, red) * (1.0f / 128.0f);
    float l = dx * rsqrtf(var + 1e-5f) * g_sl[t] + be_sl[t];
    lnv[t] = l;
    __syncthreads();
    float qa = bq[t];
    #pragma unroll 4
    for (int d = 0; d < 128; d++) qa += lnv[d] * g_WqT[d * Dc + t];
    g_q[bs * Dc + t] = qa;
}

// ---------------- stepB: dots, softmax over slots, partial updates ------
// grid: (8 chunks, 16 batches), 128 threads
#define KST 129
#define B_SMEM ((2*128*KST + 1024 + 1024 + 32) * 4)
__global__ void stepB_kernel(int f, int emit, float* __restrict__ out_attn) {
    extern __shared__ float sm[];
    float* ks   = sm;                    // 128*129
    float* vs   = ks + 128 * KST;        // 128*129
    float* qs   = vs + 128 * KST;        // 8*128
    float* as   = qs + 1024;             // 8*128
    float* sred = as + 1024;             // 8*4

    const int t = threadIdx.x;
    const int chunk = blockIdx.x;        // token chunk of 128
    const int b = blockIdx.y;
    const int bf = b * NFc + f;
    const float* kg = g_K + (size_t)bf * Nc * Dc + (size_t)chunk * 128 * Dc;
    const float* vg = g_V + (size_t)bf * Nc * Dc + (size_t)chunk * 128 * Dc;

    for (int idx = t * 4; idx < 128 * Dc; idx += 512) {
        int r = idx >> 7, d = idx & 127;
        float4 kv = *(const float4*)(kg + idx);
        float* kp = ks + r * KST + d;
        kp[0] = kv.x; kp[1] = kv.y; kp[2] = kv.z; kp[3] = kv.w;
        float4 vv = *(const float4*)(vg + idx);
        float* vp = vs + r * KST + d;
        vp[0] = vv.x; vp[1] = vv.y; vp[2] = vv.z; vp[3] = vv.w;
    }
    for (int idx = t; idx < Sc * Dc; idx += 128) qs[idx] = g_q[b * Sc * Dc + idx];
    __syncthreads();

    // dots for my token (n = chunk*128 + t), 8 slots
    float dots[8];
    #pragma unroll
    for (int s2 = 0; s2 < 8; s2++) dots[s2] = 0.0f;
    #pragma unroll 4
    for (int d = 0; d < 128; d++) {
        float kv = ks[t * KST + d];
        #pragma unroll
        for (int s2 = 0; s2 < 8; s2++) dots[s2] += qs[s2 * Dc + d] * kv;
    }
    float mx = -1e30f;
    #pragma unroll
    for (int s2 = 0; s2 < 8; s2++) { dots[s2] *= SCALEc; mx = fmaxf(mx, dots[s2]); }
    float e[8], ssum = 0.0f;
    #pragma unroll
    for (int s2 = 0; s2 < 8; s2++) { e[s2] = expf(dots[s2] - mx); ssum += e[s2]; }
    float inv = 1.0f / ssum;
    float a[8];
    #pragma unroll
    for (int s2 = 0; s2 < 8; s2++) { a[s2] = e[s2] * inv + EPSc; as[s2 * 128 + t] = a[s2]; }

    if (emit) {
        float* oa = out_attn + (size_t)bf * Sc * Nc + (size_t)chunk * 128 + t;
        #pragma unroll
        for (int s2 = 0; s2 < 8; s2++) oa[(size_t)s2 * Nc] = a[s2];
    }

    // rowsum partials
    const int lane = t & 31, warp = t >> 5;
    #pragma unroll
    for (int s2 = 0; s2 < 8; s2++) {
        float v = a[s2];
        #pragma unroll
        for (int o = 16; o; o >>= 1) v += __shfl_xor_sync(0xffffffffu, v, o);
        if (lane == 0) sred[s2 * 4 + warp] = v;
    }
    __syncthreads();
    if (t < 8) {
        g_rspart[chunk * BSc + b * Sc + t] =
            sred[t * 4 + 0] + sred[t * 4 + 1] + sred[t * 4 + 2] + sred[t * 4 + 3];
    }

    // partial updates: up[s][d=t] = sum_n a[s][n] * v[n][d]
    float up[8];
    #pragma unroll
    for (int s2 = 0; s2 < 8; s2++) up[s2] = 0.0f;
    #pragma unroll 2
    for (int n = 0; n < 128; n++) {
        float vv = vs[n * KST + t];
        #pragma unroll
        for (int s2 = 0; s2 < 8; s2++) up[s2] += as[s2 * 128 + n] * vv;
    }
    #pragma unroll
    for (int s2 = 0; s2 < 8; s2++)
        g_Upart[(chunk * BSc + b * Sc + s2) * Dc + t] = up[s2];
}

// ---------------- stepC: finalize updates, GRU, FF, next q --------------
// grid: 128 blocks (one per b*8+s), 128 threads
__global__ void stepC_kernel(int f, int emit, float* __restrict__ out_slots,
                             const float* __restrict__ bih, const float* __restrict__ bhh,
                             const float* __restrict__ g_ff, const float* __restrict__ be_ff,
                             const float* __restrict__ b1, const float* __restrict__ b2,
                             const float* __restrict__ g_sl, const float* __restrict__ be_sl,
                             const float* __restrict__ bq) {
    __shared__ float us[Dc], hs[Dc], ffs[Dc], hid[Dc], ln2[Dc], red[4];
    const int t = threadIdx.x;
    const int bs = blockIdx.x;

    float usum = 0.0f, rsum = 0.0f;
    #pragma unroll
    for (int c = 0; c < 8; c++) {
        usum += g_Upart[(c * BSc + bs) * Dc + t];
        rsum += g_rspart[c * BSc + bs];
    }
    float u = usum / rsum;
    float h = g_slots[bs * Dc + t];
    us[t] = u; hs[t] = h;
    __syncthreads();

    float a_r = 0, a_z = 0, a_n = 0, b_r = 0, b_z = 0, b_n = 0;
    #pragma unroll 4
    for (int d = 0; d < 128; d++) {
        float ud = us[d], hd = hs[d];
        const float* wi = g_WihT + d * 384;
        const float* wh = g_WhhT + d * 384;
        a_r += ud * wi[t];       b_r += hd * wh[t];
        a_z += ud * wi[128 + t]; b_z += hd * wh[128 + t];
        a_n += ud * wi[256 + t]; b_n += hd * wh[256 + t];
    }
    float r = sigmoidf_(a_r + bih[t]       + b_r + bhh[t]);
    float z = sigmoidf_(a_z + bih[128 + t] + b_z + bhh[128 + t]);
    float nn = tanhf(a_n + bih[256 + t] + r * (b_n + bhh[256 + t]));
    float hg = (1.0f - z) * nn + z * h;

    // FF: LN(hg) with g_ff
    float m = blocksum128(hg, red) * (1.0f / 128.0f);
    float dx = hg - m;
    float var = blocksum128(dx * dx, red) * (1.0f / 128.0f);
    float ffv = dx * rsqrtf(var + 1e-5f) * g_ff[t] + be_ff[t];
    ffs[t] = ffv;
    __syncthreads();
    float hacc = b1[t];
    #pragma unroll 4
    for (int d = 0; d < 128; d++) hacc += ffs[d] * g_W1T[d * Dc + t];
    hid[t] = fmaxf(hacc, 0.0f);
    __syncthreads();
    float oacc = b2[t];
    #pragma unroll 4
    for (int d = 0; d < 128; d++) oacc += hid[d] * g_W2T[d * Dc + t];
    float snew = hg + oacc;
    g_slots[bs * Dc + t] = snew;
    if (emit) {
        int b = bs >> 3, s = bs & 7;
        out_slots[(((size_t)b * NFc + f) * Sc + s) * Dc + t] = snew;
    }

    // next q = LN(snew; g_sl) @ WqT + bq
    float m2 = blocksum128(snew, red) * (1.0f / 128.0f);
    float dx2 = snew - m2;
    float var2 = blocksum128(dx2 * dx2, red) * (1.0f / 128.0f);
    float l2 = dx2 * rsqrtf(var2 + 1e-5f) * g_sl[t] + be_sl[t];
    ln2[t] = l2;
    __syncthreads();
    float qa = bq[t];
    #pragma unroll 4
    for (int d = 0; d < 128; d++) qa += ln2[d] * g_WqT[d * Dc + t];
    g_q[bs * Dc + t] = qa;
}

// ---------------- launch ----------------
extern "C" void kernel_launch(void* const* d_in, const int* in_sizes, int n_in,
                              void* d_out, int out_size) {
    const float* inputs     = (const float*)d_in[0];
    const float* slots_init = (const float*)d_in[1];
    const float* Wq  = (const float*)d_in[2];
    const float* bq  = (const float*)d_in[3];
    const float* Wk  = (const float*)d_in[4];
    const float* bk  = (const float*)d_in[5];
    const float* Wv  = (const float*)d_in[6];
    const float* bv  = (const float*)d_in[7];
    const float* W1  = (const float*)d_in[8];
    const float* b1  = (const float*)d_in[9];
    const float* W2  = (const float*)d_in[10];
    const float* b2  = (const float*)d_in[11];
    const float* Wih = (const float*)d_in[12];
    const float* Whh = (const float*)d_in[13];
    const float* bih = (const float*)d_in[14];
    const float* bhh = (const float*)d_in[15];
    const float* g_in  = (const float*)d_in[16];
    const float* be_in = (const float*)d_in[17];
    const float* g_sl  = (const float*)d_in[18];
    const float* be_sl = (const float*)d_in[19];
    const float* g_ff  = (const float*)d_in[20];
    const float* be_ff = (const float*)d_in[21];

    float* out = (float*)d_out;
    float* out_slots = out;                          // [B,NF,S,D]
    float* out_attn  = out + (size_t)Bc * NFc * Sc * Dc;   // [B,NF,S,N]

    cudaFuncSetAttribute(k0_kernel, cudaFuncAttributeMaxDynamicSharedMemorySize, K0_SMEM);
    cudaFuncSetAttribute(stepB_kernel, cudaFuncAttributeMaxDynamicSharedMemorySize, B_SMEM);

    prep_kernel<<<192, 256>>>(Wq, W1, W2, Wih, Whh);
    k0_kernel<<<dim3(Nc / 32, Bc * NFc), 128, K0_SMEM>>>(inputs, Wk, bk, Wv, bv, g_in, be_in);
    init_kernel<<<BSc, Dc>>>(slots_init, g_sl, be_sl, bq);

    for (int step = 0; step < NFc + 1; step++) {
        int f = (step == 0) ? 0 : step - 1;
        int emit = (step > 0) ? 1 : 0;
        stepB_kernel<<<dim3(Nc / 128, Bc), 128, B_SMEM>>>(f, emit, out_attn);
        stepC_kernel<<<BSc, Dc>>>(f, emit, out_slots,
                                  bih, bhh, g_ff, be_ff, b1, b2, g_sl, be_sl, bq);
    }
}

// round 5
// speedup vs baseline: 1.8723x; 1.8723x over previous
#include <cuda_runtime.h>
#include <cuda_bf16.h>
#include <cstdint>

#define Bc   16
#define NFc  16
#define Nc   1024
#define Dc   128
#define Sc   8
#define Hc   128
#define BSc  (Bc*Sc)          // 128
#define Mtot (Bc*NFc*Nc)      // 262144
#define NCHUNK 32
#define SCALEc 0.08838834764831845f
#define EPSc   1e-8f

// ---------------- device scratch (no allocations allowed) ----------------
__device__ float g_K[Bc*NFc*Nc*Dc];          // 134 MB
__device__ float g_V[Bc*NFc*Nc*Dc];          // 134 MB
__device__ __nv_bfloat16 g_Xhi[(size_t)Mtot*Dc];   // 67 MB
__device__ __nv_bfloat16 g_Xlo[(size_t)Mtot*Dc];   // 67 MB
__device__ __nv_bfloat16 g_Wkvhi[2*Dc*Dc];   // [0]=Wk, [1]=Wv, layout [n][k]
__device__ __nv_bfloat16 g_Wkvlo[2*Dc*Dc];
__device__ float g_q[BSc*Dc];
__device__ float g_slots[BSc*Dc];
__device__ float g_Upart[NCHUNK*BSc*Dc];     // 2 MB
__device__ float g_rspart[NCHUNK*BSc];
__device__ float g_WqT[Dc*Dc];
__device__ float g_W1T[Dc*Hc];
__device__ float g_W2T[Hc*Dc];
__device__ float g_WihT[Dc*3*Dc];
__device__ float g_WhhT[Dc*3*Dc];

// ---------------- helpers ----------------
__device__ __forceinline__ float blocksum128(float v, float* red) {
    #pragma unroll
    for (int o = 16; o; o >>= 1) v += __shfl_xor_sync(0xffffffffu, v, o);
    int t = threadIdx.x;
    if ((t & 31) == 0) red[t >> 5] = v;
    __syncthreads();
    float r = red[0] + red[1] + red[2] + red[3];
    __syncthreads();
    return r;
}
__device__ __forceinline__ float sigmoidf_(float x) { return 1.0f / (1.0f + expf(-x)); }

// ---------------- prep: transposes + bf16 weight splits ------------------
__global__ void prep_kernel(const float* __restrict__ Wq, const float* __restrict__ W1,
                            const float* __restrict__ W2, const float* __restrict__ Wih,
                            const float* __restrict__ Whh,
                            const float* __restrict__ Wk, const float* __restrict__ Wv) {
    int idx = blockIdx.x * 256 + threadIdx.x;
    if (idx < Dc * Dc) {
        int r = idx >> 7, c = idx & 127;
        g_WqT[c * Dc + r] = Wq[idx];
        g_W1T[c * Dc + r] = W1[idx];
        g_W2T[c * Dc + r] = W2[idx];
        // bf16 splits of Wk/Wv (keep [out][in] row-major = [n][k])
        float wkv = Wk[idx];
        __nv_bfloat16 h = __float2bfloat16_rn(wkv);
        g_Wkvhi[idx] = h;
        g_Wkvlo[idx] = __float2bfloat16_rn(wkv - __bfloat162float(h));
        wkv = Wv[idx];
        h = __float2bfloat16_rn(wkv);
        g_Wkvhi[Dc*Dc + idx] = h;
        g_Wkvlo[Dc*Dc + idx] = __float2bfloat16_rn(wkv - __bfloat162float(h));
    }
    if (idx < 3 * Dc * Dc) {
        int j = idx >> 7, d = idx & 127;
        g_WihT[d * 384 + j] = Wih[idx];
        g_WhhT[d * 384 + j] = Whh[idx];
    }
}

// ---------------- ln_split: LN(x) -> bf16 hi/lo ----------------
// one warp per row; grid Mtot/8 blocks, 256 threads
__global__ void ln_split_kernel(const float* __restrict__ x,
                                const float* __restrict__ g_in, const float* __restrict__ be_in) {
    const int lane = threadIdx.x & 31;
    const int wp = threadIdx.x >> 5;
    const size_t row = (size_t)blockIdx.x * 8 + wp;
    float4 v = ((const float4*)(x + row * Dc))[lane];
    float s = v.x + v.y + v.z + v.w;
    #pragma unroll
    for (int o = 16; o; o >>= 1) s += __shfl_xor_sync(0xffffffffu, s, o);
    float m = s * (1.0f / 128.0f);
    float d0 = v.x - m, d1 = v.y - m, d2 = v.z - m, d3 = v.w - m;
    float ss = d0*d0 + d1*d1 + d2*d2 + d3*d3;
    #pragma unroll
    for (int o = 16; o; o >>= 1) ss += __shfl_xor_sync(0xffffffffu, ss, o);
    float inv = rsqrtf(ss * (1.0f / 128.0f) + 1e-5f);
    float4 gg = ((const float4*)g_in)[lane];
    float4 bb = ((const float4*)be_in)[lane];
    float y0 = d0*inv*gg.x + bb.x, y1 = d1*inv*gg.y + bb.y;
    float y2 = d2*inv*gg.z + bb.z, y3 = d3*inv*gg.w + bb.w;
    __nv_bfloat16 h0 = __float2bfloat16_rn(y0), h1 = __float2bfloat16_rn(y1);
    __nv_bfloat16 h2 = __float2bfloat16_rn(y2), h3 = __float2bfloat16_rn(y3);
    __nv_bfloat16 l0 = __float2bfloat16_rn(y0 - __bfloat162float(h0));
    __nv_bfloat16 l1 = __float2bfloat16_rn(y1 - __bfloat162float(h1));
    __nv_bfloat16 l2 = __float2bfloat16_rn(y2 - __bfloat162float(h2));
    __nv_bfloat16 l3 = __float2bfloat16_rn(y3 - __bfloat162float(h3));
    ushort4 ph = make_ushort4(*(unsigned short*)&h0, *(unsigned short*)&h1,
                              *(unsigned short*)&h2, *(unsigned short*)&h3);
    ushort4 pl = make_ushort4(*(unsigned short*)&l0, *(unsigned short*)&l1,
                              *(unsigned short*)&l2, *(unsigned short*)&l3);
    *(ushort4*)(g_Xhi + row * Dc + lane * 4) = ph;
    *(ushort4*)(g_Xlo + row * Dc + lane * 4) = pl;
}

// ---------------- gemm: K/V = Xn @ W^T via bf16 split mma.sync ----------
// grid (Mtot/128, 2): y=0 -> K, y=1 -> V. 256 threads (8 warps).
// smem: 4 tiles of [128][136] bf16 (Xhi, Xlo, Whi, Wlo) = 136 KB
#define GSTRIDE 136
#define GEMM_SMEM (4 * 128 * GSTRIDE * 2)
__device__ __forceinline__ void mma16816(float* c, const uint32_t* a, const uint32_t* b) {
    asm volatile(
        "mma.sync.aligned.m16n8k16.row.col.f32.bf16.bf16.f32 "
        "{%0,%1,%2,%3}, {%4,%5,%6,%7}, {%8,%9}, {%0,%1,%2,%3};"
        : "+f"(c[0]), "+f"(c[1]), "+f"(c[2]), "+f"(c[3])
        : "r"(a[0]), "r"(a[1]), "r"(a[2]), "r"(a[3]), "r"(b[0]), "r"(b[1]));
}
__global__ void __launch_bounds__(256, 1) gemm_kernel(const float* __restrict__ bk,
                                                      const float* __restrict__ bv) {
    extern __shared__ __nv_bfloat16 sm[];
    __nv_bfloat16* xhi_s = sm;
    __nv_bfloat16* xlo_s = xhi_s + 128 * GSTRIDE;
    __nv_bfloat16* whi_s = xlo_s + 128 * GSTRIDE;
    __nv_bfloat16* wlo_s = whi_s + 128 * GSTRIDE;

    const int t = threadIdx.x;
    const int m0 = blockIdx.x * 128;
    const int y = blockIdx.y;
    const size_t wbase = (size_t)y * Dc * Dc;

    // cooperative tile loads (16B each)
    #pragma unroll
    for (int i = 0; i < 8; i++) {
        int l = t + i * 256;
        int r = l >> 4, kc = (l & 15) * 8;
        int so = r * GSTRIDE + kc;
        *(uint4*)(xhi_s + so) = *(const uint4*)(g_Xhi + (size_t)(m0 + r) * Dc + kc);
        *(uint4*)(xlo_s + so) = *(const uint4*)(g_Xlo + (size_t)(m0 + r) * Dc + kc);
        *(uint4*)(whi_s + so) = *(const uint4*)(g_Wkvhi + wbase + (size_t)r * Dc + kc);
        *(uint4*)(wlo_s + so) = *(const uint4*)(g_Wkvlo + wbase + (size_t)r * Dc + kc);
    }
    __syncthreads();

    const int lane = t & 31, w = t >> 5;
    const int wr = (w >> 1) * 32;        // warp row base (4 row-warps)
    const int wc = (w & 1) * 64;         // warp col base (2 col-warps)
    const int g = lane >> 2, tg = lane & 3;

    float acc[2][8][4];
    #pragma unroll
    for (int mi = 0; mi < 2; mi++)
        #pragma unroll
        for (int ni = 0; ni < 8; ni++)
            #pragma unroll
            for (int j = 0; j < 4; j++) acc[mi][ni][j] = 0.0f;

    const __nv_bfloat16* Ap[3] = {xhi_s, xhi_s, xlo_s};
    const __nv_bfloat16* Bp[3] = {whi_s, wlo_s, whi_s};

    #pragma unroll
    for (int p = 0; p < 3; p++) {
        const __nv_bfloat16* As = Ap[p];
        const __nv_bfloat16* Bs = Bp[p];
        #pragma unroll
        for (int kk = 0; kk < 8; kk++) {
            const int kb = kk * 16 + tg * 2;
            uint32_t afr[2][4], bfr[8][2];
            #pragma unroll
            for (int mi = 0; mi < 2; mi++) {
                int r = wr + mi * 16 + g;
                afr[mi][0] = *(const uint32_t*)(As + r * GSTRIDE + kb);
                afr[mi][1] = *(const uint32_t*)(As + (r + 8) * GSTRIDE + kb);
                afr[mi][2] = *(const uint32_t*)(As + r * GSTRIDE + kb + 8);
                afr[mi][3] = *(const uint32_t*)(As + (r + 8) * GSTRIDE + kb + 8);
            }
            #pragma unroll
            for (int ni = 0; ni < 8; ni++) {
                int n = wc + ni * 8 + g;
                bfr[ni][0] = *(const uint32_t*)(Bs + n * GSTRIDE + kb);
                bfr[ni][1] = *(const uint32_t*)(Bs + n * GSTRIDE + kb + 8);
            }
            #pragma unroll
            for (int mi = 0; mi < 2; mi++)
                #pragma unroll
                for (int ni = 0; ni < 8; ni++)
                    mma16816(acc[mi][ni], afr[mi], bfr[ni]);
        }
    }

    float* outp = (y == 0) ? g_K : g_V;
    const float* bias = (y == 0) ? bk : bv;
    #pragma unroll
    for (int mi = 0; mi < 2; mi++) {
        #pragma unroll
        for (int ni = 0; ni < 8; ni++) {
            int r0 = m0 + wr + mi * 16 + g;
            int c0 = wc + ni * 8 + tg * 2;
            float b0 = bias[c0], b1 = bias[c0 + 1];
            float2 v0 = make_float2(acc[mi][ni][0] + b0, acc[mi][ni][1] + b1);
            float2 v1 = make_float2(acc[mi][ni][2] + b0, acc[mi][ni][3] + b1);
            *(float2*)(outp + (size_t)r0 * Dc + c0) = v0;
            *(float2*)(outp + (size_t)(r0 + 8) * Dc + c0) = v1;
        }
    }
}

// ---------------- init: slots = broadcast(slots_init); q0 ----------------
__global__ void init_kernel(const float* __restrict__ slots_init,
                            const float* __restrict__ g_sl, const float* __restrict__ be_sl,
                            const float* __restrict__ bq) {
    __shared__ float lnv[Dc];
    __shared__ float red[4];
    const int t = threadIdx.x;
    const int bs = blockIdx.x;           // b*8 + s
    const int s = bs & 7;
    float v = slots_init[s * Dc + t];
    g_slots[bs * Dc + t] = v;
    float m = blocksum128(v, red) * (1.0f / 128.0f);
    float dx = v - m;
    float var = blocksum128(dx * dx, red) * (1.0f / 128.0f);
    float l = dx * rsqrtf(var + 1e-5f) * g_sl[t] + be_sl[t];
    lnv[t] = l;
    __syncthreads();
    float qa = bq[t];
    #pragma unroll 4
    for (int d = 0; d < 128; d++) qa += lnv[d] * g_WqT[d * Dc + t];
    g_q[bs * Dc + t] = qa;
}

// ---------------- stepB: dots, softmax over slots, partial updates ------
// grid (32 chunks of 32 tokens, 16 batches), 256 threads
#define KVST 132
#define QST  129
#define AST  33
__global__ void __launch_bounds__(256, 4) stepB_kernel(int f, int emit, float* __restrict__ out_attn) {
    __shared__ float ks[32 * KVST];
    __shared__ float vs[32 * KVST];
    __shared__ float qs[Sc * QST];
    __shared__ float as[Sc * AST];

    const int t = threadIdx.x;
    const int chunk = blockIdx.x;        // 32-token chunk
    const int b = blockIdx.y;
    const int bf = b * NFc + f;
    const float* kg = g_K + (size_t)bf * Nc * Dc + (size_t)chunk * 32 * Dc;
    const float* vg = g_V + (size_t)bf * Nc * Dc + (size_t)chunk * 32 * Dc;

    // loads: 32 rows x 128 d, float4: 1024 per array / 256 threads = 4 each
    #pragma unroll
    for (int i = 0; i < 4; i++) {
        int l = t + i * 256;             // float4 index
        int r = l >> 5, d = (l & 31) * 4;
        float4 kv = *(const float4*)(kg + r * Dc + d);
        *(float4*)(ks + r * KVST + d) = kv;
        float4 vv = *(const float4*)(vg + r * Dc + d);
        *(float4*)(vs + r * KVST + d) = vv;
    }
    #pragma unroll
    for (int i = 0; i < 4; i++) {
        int idx = t + i * 256;
        int s = idx >> 7, d = idx & 127;
        qs[s * QST + d] = g_q[b * Sc * Dc + idx];
    }
    __syncthreads();

    // dots: thread -> (token tt, slot s)
    const int tt = t >> 3;               // 0..31
    const int s = t & 7;                 // 0..7
    float dot = 0.0f;
    #pragma unroll 8
    for (int d = 0; d < 128; d++) dot += qs[s * QST + d] * ks[tt * KVST + d];
    dot *= SCALEc;
    // softmax over the 8 slots sharing tt (consecutive lanes)
    float mx = dot;
    #pragma unroll
    for (int o = 4; o; o >>= 1) mx = fmaxf(mx, __shfl_xor_sync(0xffffffffu, mx, o));
    float e = expf(dot - mx);
    float ssum = e;
    #pragma unroll
    for (int o = 4; o; o >>= 1) ssum += __shfl_xor_sync(0xffffffffu, ssum, o);
    float a = e / ssum + EPSc;
    as[s * AST + tt] = a;

    if (emit) {
        out_attn[(size_t)bf * Sc * Nc + (size_t)s * Nc + chunk * 32 + tt] = a;
    }
    __syncthreads();

    // rowsum partials (per slot over this chunk's 32 tokens)
    if (t < 8) {
        float rs = 0.0f;
        #pragma unroll
        for (int n = 0; n < 32; n++) rs += as[t * AST + n];
        g_rspart[chunk * BSc + b * Sc + t] = rs;
    }

    // partial updates: up[s][d] = sum_n a[s][n] * v[n][d]
    const int d = t & 127;
    const int grp = t >> 7;              // 0 or 1 -> slots 0-3 / 4-7
    #pragma unroll
    for (int si = 0; si < 4; si++) {
        int s2 = grp * 4 + si;
        float up = 0.0f;
        #pragma unroll 8
        for (int n = 0; n < 32; n++) up += as[s2 * AST + n] * vs[n * KVST + d];
        g_Upart[(chunk * BSc + b * Sc + s2) * Dc + d] = up;
    }
}

// ---------------- stepC: finalize updates, GRU, FF, next q --------------
__global__ void stepC_kernel(int f, int emit, float* __restrict__ out_slots,
                             const float* __restrict__ bih, const float* __restrict__ bhh,
                             const float* __restrict__ g_ff, const float* __restrict__ be_ff,
                             const float* __restrict__ b1, const float* __restrict__ b2,
                             const float* __restrict__ g_sl, const float* __restrict__ be_sl,
                             const float* __restrict__ bq) {
    __shared__ float us[Dc], hs[Dc], ffs[Dc], hid[Dc], ln2[Dc], red[4];
    const int t = threadIdx.x;
    const int bs = blockIdx.x;

    float usum = 0.0f, rsum = 0.0f;
    #pragma unroll 8
    for (int c = 0; c < NCHUNK; c++) {
        usum += g_Upart[(c * BSc + bs) * Dc + t];
        rsum += g_rspart[c * BSc + bs];
    }
    float u = usum / rsum;
    float h = g_slots[bs * Dc + t];
    us[t] = u; hs[t] = h;
    __syncthreads();

    float a_r = 0, a_z = 0, a_n = 0, b_r = 0, b_z = 0, b_n = 0;
    #pragma unroll 4
    for (int d = 0; d < 128; d++) {
        float ud = us[d], hd = hs[d];
        const float* wi = g_WihT + d * 384;
        const float* wh = g_WhhT + d * 384;
        a_r += ud * wi[t];       b_r += hd * wh[t];
        a_z += ud * wi[128 + t]; b_z += hd * wh[128 + t];
        a_n += ud * wi[256 + t]; b_n += hd * wh[256 + t];
    }
    float r = sigmoidf_(a_r + bih[t]       + b_r + bhh[t]);
    float z = sigmoidf_(a_z + bih[128 + t] + b_z + bhh[128 + t]);
    float nn = tanhf(a_n + bih[256 + t] + r * (b_n + bhh[256 + t]));
    float hg = (1.0f - z) * nn + z * h;

    float m = blocksum128(hg, red) * (1.0f / 128.0f);
    float dx = hg - m;
    float var = blocksum128(dx * dx, red) * (1.0f / 128.0f);
    float ffv = dx * rsqrtf(var + 1e-5f) * g_ff[t] + be_ff[t];
    ffs[t] = ffv;
    __syncthreads();
    float hacc = b1[t];
    #pragma unroll 4
    for (int d = 0; d < 128; d++) hacc += ffs[d] * g_W1T[d * Dc + t];
    hid[t] = fmaxf(hacc, 0.0f);
    __syncthreads();
    float oacc = b2[t];
    #pragma unroll 4
    for (int d = 0; d < 128; d++) oacc += hid[d] * g_W2T[d * Dc + t];
    float snew = hg + oacc;
    g_slots[bs * Dc + t] = snew;
    if (emit) {
        int b = bs >> 3, s = bs & 7;
        out_slots[(((size_t)b * NFc + f) * Sc + s) * Dc + t] = snew;
    }

    float m2 = blocksum128(snew, red) * (1.0f / 128.0f);
    float dx2 = snew - m2;
    float var2 = blocksum128(dx2 * dx2, red) * (1.0f / 128.0f);
    float l2 = dx2 * rsqrtf(var2 + 1e-5f) * g_sl[t] + be_sl[t];
    ln2[t] = l2;
    __syncthreads();
    float qa = bq[t];
    #pragma unroll 4
    for (int d = 0; d < 128; d++) qa += ln2[d] * g_WqT[d * Dc + t];
    g_q[bs * Dc + t] = qa;
}

// ---------------- launch ----------------
extern "C" void kernel_launch(void* const* d_in, const int* in_sizes, int n_in,
                              void* d_out, int out_size) {
    const float* inputs     = (const float*)d_in[0];
    const float* slots_init = (const float*)d_in[1];
    const float* Wq  = (const float*)d_in[2];
    const float* bq  = (const float*)d_in[3];
    const float* Wk  = (const float*)d_in[4];
    const float* bk  = (const float*)d_in[5];
    const float* Wv  = (const float*)d_in[6];
    const float* bv  = (const float*)d_in[7];
    const float* W1  = (const float*)d_in[8];
    const float* b1  = (const float*)d_in[9];
    const float* W2  = (const float*)d_in[10];
    const float* b2  = (const float*)d_in[11];
    const float* Wih = (const float*)d_in[12];
    const float* Whh = (const float*)d_in[13];
    const float* bih = (const float*)d_in[14];
    const float* bhh = (const float*)d_in[15];
    const float* g_in  = (const float*)d_in[16];
    const float* be_in = (const float*)d_in[17];
    const float* g_sl  = (const float*)d_in[18];
    const float* be_sl = (const float*)d_in[19];
    const float* g_ff  = (const float*)d_in[20];
    const float* be_ff = (const float*)d_in[21];

    float* out = (float*)d_out;
    float* out_slots = out;                                 // [B,NF,S,D]
    float* out_attn  = out + (size_t)Bc * NFc * Sc * Dc;    // [B,NF,S,N]

    cudaFuncSetAttribute(gemm_kernel, cudaFuncAttributeMaxDynamicSharedMemorySize, GEMM_SMEM);

    prep_kernel<<<192, 256>>>(Wq, W1, W2, Wih, Whh, Wk, Wv);
    ln_split_kernel<<<Mtot / 8, 256>>>(inputs, g_in, be_in);
    gemm_kernel<<<dim3(Mtot / 128, 2), 256, GEMM_SMEM>>>(bk, bv);
    init_kernel<<<BSc, Dc>>>(slots_init, g_sl, be_sl, bq);

    for (int step = 0; step < NFc + 1; step++) {
        int f = (step == 0) ? 0 : step - 1;
        int emit = (step > 0) ? 1 : 0;
        stepB_kernel<<<dim3(NCHUNK, Bc), 256>>>(f, emit, out_attn);
        stepC_kernel<<<BSc, Dc>>>(f, emit, out_slots,
                                  bih, bhh, g_ff, be_ff, b1, b2, g_sl, be_sl, bq);
    }
}

// round 6
// speedup vs baseline: 2.7058x; 1.4452x over previous
#include <cuda_runtime.h>
#include <cuda_bf16.h>
#include <cstdint>

#define Bc   16
#define NFc  16
#define Nc   1024
#define Dc   128
#define Sc   8
#define Hc   128
#define BSc  (Bc*Sc)          // 128
#define Mtot (Bc*NFc*Nc)      // 262144
#define NCHUNK 32
#define SCALEc 0.08838834764831845f
#define EPSc   1e-8f

// ---------------- device scratch (no allocations allowed) ----------------
__device__ float g_K[Bc*NFc*Nc*Dc];          // 134 MB
__device__ float g_V[Bc*NFc*Nc*Dc];          // 134 MB
__device__ __nv_bfloat16 g_Wkvhi[2*Dc*Dc];   // [0]=Wk, [1]=Wv, layout [n][k]
__device__ __nv_bfloat16 g_Wkvlo[2*Dc*Dc];
__device__ float g_q[BSc*Dc];
__device__ float g_slots[BSc*Dc];
__device__ float g_Upart[NCHUNK*BSc*Dc];     // 2 MB
__device__ float g_rspart[NCHUNK*BSc];
__device__ float g_WqT[Dc*Dc];
__device__ float g_W1T[Dc*Hc];
__device__ float g_W2T[Hc*Dc];
__device__ float g_WihT[Dc*3*Dc];
__device__ float g_WhhT[Dc*3*Dc];

// ---------------- helpers ----------------
__device__ __forceinline__ float blocksum128(float v, float* red) {
    #pragma unroll
    for (int o = 16; o; o >>= 1) v += __shfl_xor_sync(0xffffffffu, v, o);
    int t = threadIdx.x;
    if ((t & 31) == 0) red[t >> 5] = v;
    __syncthreads();
    float r = red[0] + red[1] + red[2] + red[3];
    __syncthreads();
    return r;
}
// 384-thread variant; callers pass 0 for t>=128
__device__ __forceinline__ float blocksum384(float v, float* red) {
    #pragma unroll
    for (int o = 16; o; o >>= 1) v += __shfl_xor_sync(0xffffffffu, v, o);
    int t = threadIdx.x;
    if ((t & 31) == 0) red[t >> 5] = v;
    __syncthreads();
    float r = 0.0f;
    #pragma unroll
    for (int i = 0; i < 12; i++) r += red[i];
    __syncthreads();
    return r;
}
__device__ __forceinline__ float sigmoidf_(float x) { return 1.0f / (1.0f + expf(-x)); }

__device__ __forceinline__ void mma16816(float* c, const uint32_t* a, const uint32_t* b) {
    asm volatile(
        "mma.sync.aligned.m16n8k16.row.col.f32.bf16.bf16.f32 "
        "{%0,%1,%2,%3}, {%4,%5,%6,%7}, {%8,%9}, {%0,%1,%2,%3};"
        : "+f"(c[0]), "+f"(c[1]), "+f"(c[2]), "+f"(c[3])
        : "r"(a[0]), "r"(a[1]), "r"(a[2]), "r"(a[3]), "r"(b[0]), "r"(b[1]));
}
__device__ __forceinline__ void ldsm_x4(uint32_t* r, const void* p) {
    uint32_t addr = (uint32_t)__cvta_generic_to_shared(p);
    asm volatile("ldmatrix.sync.aligned.m8n8.x4.shared.b16 {%0,%1,%2,%3}, [%4];"
        : "=r"(r[0]), "=r"(r[1]), "=r"(r[2]), "=r"(r[3]) : "r"(addr));
}

// ---------------- prep: transposes + bf16 weight splits ------------------
__global__ void prep_kernel(const float* __restrict__ Wq, const float* __restrict__ W1,
                            const float* __restrict__ W2, const float* __restrict__ Wih,
                            const float* __restrict__ Whh,
                            const float* __restrict__ Wk, const float* __restrict__ Wv) {
    int idx = blockIdx.x * 256 + threadIdx.x;
    if (idx < Dc * Dc) {
        int r = idx >> 7, c = idx & 127;
        g_WqT[c * Dc + r] = Wq[idx];
        g_W1T[c * Dc + r] = W1[idx];
        g_W2T[c * Dc + r] = W2[idx];
        float wkv = Wk[idx];
        __nv_bfloat16 h = __float2bfloat16_rn(wkv);
        g_Wkvhi[idx] = h;
        g_Wkvlo[idx] = __float2bfloat16_rn(wkv - __bfloat162float(h));
        wkv = Wv[idx];
        h = __float2bfloat16_rn(wkv);
        g_Wkvhi[Dc*Dc + idx] = h;
        g_Wkvlo[Dc*Dc + idx] = __float2bfloat16_rn(wkv - __bfloat162float(h));
    }
    if (idx < 3 * Dc * Dc) {
        int j = idx >> 7, d = idx & 127;
        g_WihT[d * 384 + j] = Wih[idx];
        g_WhhT[d * 384 + j] = Whh[idx];
    }
}

// ---------------- gemm2: fused LN + split-bf16 mma for K and V ----------
// grid Mtot/128/NTILES blocks, 256 threads (8 warps, 4x2 warp tiling)
#define GST 136
#define NTILES 4
#define GEMM2_SMEM (6 * 128 * GST * 2)     // 208896 B
__global__ void __launch_bounds__(256, 1) gemm2_kernel(
        const float* __restrict__ x,
        const float* __restrict__ g_in, const float* __restrict__ be_in,
        const float* __restrict__ bk, const float* __restrict__ bv) {
    extern __shared__ __nv_bfloat16 sm[];
    __nv_bfloat16* xhi = sm;
    __nv_bfloat16* xlo = xhi + 128 * GST;
    __nv_bfloat16* wts = xlo + 128 * GST;  // [4][128][GST]: Khi, Klo, Vhi, Vlo

    const int t = threadIdx.x;
    const int lane = t & 31, w = t >> 5;

    // load 4 weight tiles (32 uint4 per thread)
    #pragma unroll
    for (int i = 0; i < 32; i++) {
        int l = t + i * 256;
        int tile = l >> 11;
        int rem = l & 2047;
        int r = rem >> 4, kc = (rem & 15) * 8;
        const __nv_bfloat16* src =
            (tile == 0) ? g_Wkvhi : (tile == 1) ? g_Wkvlo :
            (tile == 2) ? (g_Wkvhi + Dc*Dc) : (g_Wkvlo + Dc*Dc);
        *(uint4*)(wts + tile * 128 * GST + r * GST + kc) = *(const uint4*)(src + r * Dc + kc);
    }

    float4 gg = ((const float4*)g_in)[lane];
    float4 bb = ((const float4*)be_in)[lane];

    const int wr = (w >> 1) * 32;
    const int wc = (w & 1) * 64;
    const int g = lane >> 2, tg = lane & 3;

    for (int it = 0; it < NTILES; it++) {
        __syncthreads();   // weights ready (it=0) / prior mma reads done
        const size_t m0 = ((size_t)blockIdx.x * NTILES + it) * 128;

        // LN 16 rows per warp -> split bf16 into xhi/xlo
        for (int r = w; r < 128; r += 8) {
            float4 v = ((const float4*)(x + (m0 + r) * Dc))[lane];
            float s = v.x + v.y + v.z + v.w;
            #pragma unroll
            for (int o = 16; o; o >>= 1) s += __shfl_xor_sync(0xffffffffu, s, o);
            float m = s * (1.0f / 128.0f);
            float d0 = v.x - m, d1 = v.y - m, d2 = v.z - m, d3 = v.w - m;
            float ss = d0*d0 + d1*d1 + d2*d2 + d3*d3;
            #pragma unroll
            for (int o = 16; o; o >>= 1) ss += __shfl_xor_sync(0xffffffffu, ss, o);
            float inv = rsqrtf(ss * (1.0f / 128.0f) + 1e-5f);
            float y0 = d0*inv*gg.x + bb.x, y1 = d1*inv*gg.y + bb.y;
            float y2 = d2*inv*gg.z + bb.z, y3 = d3*inv*gg.w + bb.w;
            __nv_bfloat16 h0 = __float2bfloat16_rn(y0), h1 = __float2bfloat16_rn(y1);
            __nv_bfloat16 h2 = __float2bfloat16_rn(y2), h3 = __float2bfloat16_rn(y3);
            __nv_bfloat16 l0 = __float2bfloat16_rn(y0 - __bfloat162float(h0));
            __nv_bfloat16 l1 = __float2bfloat16_rn(y1 - __bfloat162float(h1));
            __nv_bfloat16 l2 = __float2bfloat16_rn(y2 - __bfloat162float(h2));
            __nv_bfloat16 l3 = __float2bfloat16_rn(y3 - __bfloat162float(h3));
            ushort4 ph = make_ushort4(*(unsigned short*)&h0, *(unsigned short*)&h1,
                                      *(unsigned short*)&h2, *(unsigned short*)&h3);
            ushort4 pl = make_ushort4(*(unsigned short*)&l0, *(unsigned short*)&l1,
                                      *(unsigned short*)&l2, *(unsigned short*)&l3);
            *(ushort4*)(xhi + r * GST + lane * 4) = ph;
            *(ushort4*)(xlo + r * GST + lane * 4) = pl;
        }
        __syncthreads();

        #pragma unroll
        for (int y = 0; y < 2; y++) {
            const __nv_bfloat16* whi = wts + (y * 2 + 0) * 128 * GST;
            const __nv_bfloat16* wlo = wts + (y * 2 + 1) * 128 * GST;
            float acc[2][8][4];
            #pragma unroll
            for (int mi = 0; mi < 2; mi++)
                #pragma unroll
                for (int ni = 0; ni < 8; ni++)
                    #pragma unroll
                    for (int j = 0; j < 4; j++) acc[mi][ni][j] = 0.0f;

            #pragma unroll
            for (int p = 0; p < 3; p++) {
                const __nv_bfloat16* As = (p == 2) ? xlo : xhi;
                const __nv_bfloat16* Bs = (p == 1) ? wlo : whi;
                #pragma unroll
                for (int kk = 0; kk < 8; kk++) {
                    const int kb = kk * 16;
                    uint32_t afr[2][4], bfr[8][2];
                    #pragma unroll
                    for (int mi = 0; mi < 2; mi++) {
                        int row = wr + mi * 16 + (lane & 15);
                        int kc = kb + (lane >> 4) * 8;
                        ldsm_x4(afr[mi], As + row * GST + kc);
                    }
                    #pragma unroll
                    for (int nj = 0; nj < 4; nj++) {
                        int n = wc + nj * 16 + (lane & 7) + ((lane >> 4) << 3);
                        int kc = kb + ((lane >> 3) & 1) * 8;
                        uint32_t b4[4];
                        ldsm_x4(b4, Bs + n * GST + kc);
                        bfr[2*nj][0] = b4[0]; bfr[2*nj][1] = b4[1];
                        bfr[2*nj+1][0] = b4[2]; bfr[2*nj+1][1] = b4[3];
                    }
                    #pragma unroll
                    for (int mi = 0; mi < 2; mi++)
                        #pragma unroll
                        for (int ni = 0; ni < 8; ni++)
                            mma16816(acc[mi][ni], afr[mi], bfr[ni]);
                }
            }

            float* outp = y ? g_V : g_K;
            const float* bias = y ? bv : bk;
            #pragma unroll
            for (int mi = 0; mi < 2; mi++) {
                #pragma unroll
                for (int ni = 0; ni < 8; ni++) {
                    size_t r0 = m0 + wr + mi * 16 + g;
                    int c0 = wc + ni * 8 + tg * 2;
                    float b0 = bias[c0], b1 = bias[c0 + 1];
                    float2 v0 = make_float2(acc[mi][ni][0] + b0, acc[mi][ni][1] + b1);
                    float2 v1 = make_float2(acc[mi][ni][2] + b0, acc[mi][ni][3] + b1);
                    *(float2*)(outp + r0 * Dc + c0) = v0;
                    *(float2*)(outp + (r0 + 8) * Dc + c0) = v1;
                }
            }
        }
    }
}

// ---------------- init: slots = broadcast(slots_init); q0 ----------------
__global__ void init_kernel(const float* __restrict__ slots_init,
                            const float* __restrict__ g_sl, const float* __restrict__ be_sl,
                            const float* __restrict__ bq) {
    __shared__ float lnv[Dc];
    __shared__ float red[4];
    const int t = threadIdx.x;
    const int bs = blockIdx.x;           // b*8 + s
    const int s = bs & 7;
    float v = slots_init[s * Dc + t];
    g_slots[bs * Dc + t] = v;
    float m = blocksum128(v, red) * (1.0f / 128.0f);
    float dx = v - m;
    float var = blocksum128(dx * dx, red) * (1.0f / 128.0f);
    float l = dx * rsqrtf(var + 1e-5f) * g_sl[t] + be_sl[t];
    lnv[t] = l;
    __syncthreads();
    float qa = bq[t];
    #pragma unroll 4
    for (int d = 0; d < 128; d++) qa += lnv[d] * g_WqT[d * Dc + t];
    g_q[bs * Dc + t] = qa;
}

// ---------------- stepB: dots, softmax over slots, partial updates ------
// grid (32 chunks of 32 tokens, 16 batches), 256 threads
#define KVST 132
#define QST  129
#define AST  33
__global__ void __launch_bounds__(256, 4) stepB_kernel(int f, int emit, float* __restrict__ out_attn) {
    __shared__ float ks[32 * KVST];
    __shared__ float vs[32 * KVST];
    __shared__ float qs[Sc * QST];
    __shared__ float as[Sc * AST];

    const int t = threadIdx.x;
    const int chunk = blockIdx.x;        // 32-token chunk
    const int b = blockIdx.y;
    const int bf = b * NFc + f;
    const float* kg = g_K + (size_t)bf * Nc * Dc + (size_t)chunk * 32 * Dc;
    const float* vg = g_V + (size_t)bf * Nc * Dc + (size_t)chunk * 32 * Dc;

    #pragma unroll
    for (int i = 0; i < 4; i++) {
        int l = t + i * 256;             // float4 index
        int r = l >> 5, d = (l & 31) * 4;
        float4 kv = *(const float4*)(kg + r * Dc + d);
        *(float4*)(ks + r * KVST + d) = kv;
        float4 vv = *(const float4*)(vg + r * Dc + d);
        *(float4*)(vs + r * KVST + d) = vv;
    }
    #pragma unroll
    for (int i = 0; i < 4; i++) {
        int idx = t + i * 256;
        int s = idx >> 7, d = idx & 127;
        qs[s * QST + d] = g_q[b * Sc * Dc + idx];
    }
    __syncthreads();

    // dots: thread -> (token tt, slot s)
    const int tt = t >> 3;               // 0..31
    const int s = t & 7;                 // 0..7
    float dot = 0.0f;
    #pragma unroll 8
    for (int d = 0; d < 128; d++) dot += qs[s * QST + d] * ks[tt * KVST + d];
    dot *= SCALEc;
    float mx = dot;
    #pragma unroll
    for (int o = 4; o; o >>= 1) mx = fmaxf(mx, __shfl_xor_sync(0xffffffffu, mx, o));
    float e = expf(dot - mx);
    float ssum = e;
    #pragma unroll
    for (int o = 4; o; o >>= 1) ssum += __shfl_xor_sync(0xffffffffu, ssum, o);
    float a = e / ssum + EPSc;
    as[s * AST + tt] = a;
    __syncthreads();

    // coalesced attn emit via smem staging
    if (emit) {
        int s3 = t >> 5, n3 = t & 31;    // t<256 covers 8x32
        out_attn[(size_t)bf * Sc * Nc + (size_t)s3 * Nc + chunk * 32 + n3] = as[s3 * AST + n3];
    }

    // rowsum partials (per slot over this chunk's 32 tokens)
    if (t < 8) {
        float rs = 0.0f;
        #pragma unroll
        for (int n = 0; n < 32; n++) rs += as[t * AST + n];
        g_rspart[chunk * BSc + b * Sc + t] = rs;
    }

    // partial updates: up[s][d] = sum_n a[s][n] * v[n][d]
    const int d = t & 127;
    const int grp = t >> 7;              // 0 or 1 -> slots 0-3 / 4-7
    #pragma unroll
    for (int si = 0; si < 4; si++) {
        int s2 = grp * 4 + si;
        float up = 0.0f;
        #pragma unroll 8
        for (int n = 0; n < 32; n++) up += as[s2 * AST + n] * vs[n * KVST + d];
        g_Upart[(chunk * BSc + b * Sc + s2) * Dc + d] = up;
    }
}

// ---------------- stepC: finalize updates, GRU, FF, next q --------------
// grid 128 blocks (one per b*8+s), 384 threads
__global__ void __launch_bounds__(384) stepC_kernel(int f, int emit, float* __restrict__ out_slots,
                             const float* __restrict__ bih, const float* __restrict__ bhh,
                             const float* __restrict__ g_ff, const float* __restrict__ be_ff,
                             const float* __restrict__ b1, const float* __restrict__ b2,
                             const float* __restrict__ g_sl, const float* __restrict__ be_sl,
                             const float* __restrict__ bq) {
    __shared__ float us[Dc], hs[Dc], hgs[Dc], ffs[Dc], hid[Dc], ln2s[Dc];
    __shared__ float sgA[384], sgB[384], sgA2[384], sgB2[384];
    __shared__ float fpart[8][Dc];
    __shared__ float red[12];

    const int t = threadIdx.x;
    const int bs = blockIdx.x;

    // phase A: finalize updates
    if (t < 128) {
        float usum = 0.0f;
        #pragma unroll 8
        for (int c = 0; c < NCHUNK; c++) usum += g_Upart[(c * BSc + bs) * Dc + t];
        float rsum = 0.0f;
        #pragma unroll
        for (int c = 0; c < NCHUNK; c++) rsum += g_rspart[c * BSc + bs];
        us[t] = usum / rsum;
        hs[t] = g_slots[bs * Dc + t];
    }
    __syncthreads();

    // phase B: GRU gate GEMVs, 4 groups x 96 threads, float4 outputs
    {
        int grp = t / 96;               // 0: gi d<64, 1: gh d<64, 2: gi d>=64, 3: gh d>=64
        int q = t - grp * 96;           // 0..95 -> output quad j=4q
        const float* W = (grp & 1) ? g_WhhT : g_WihT;
        const float* xv = (grp & 1) ? hs : us;
        int d0 = (grp >> 1) * 64;
        float4 acc = make_float4(0.f, 0.f, 0.f, 0.f);
        #pragma unroll 16
        for (int i = 0; i < 64; i++) {
            int d = d0 + i;
            float4 w4 = *(const float4*)(W + d * 384 + q * 4);
            float xd = xv[d];
            acc.x += xd * w4.x; acc.y += xd * w4.y;
            acc.z += xd * w4.z; acc.w += xd * w4.w;
        }
        float* dst = (grp == 0) ? sgA : (grp == 1) ? sgB : (grp == 2) ? sgA2 : sgB2;
        *(float4*)(dst + q * 4) = acc;
    }
    __syncthreads();

    // phase C: gates + GRU + LN for FF
    float hg = 0.0f;
    if (t < 128) {
        float gi_r = sgA[t]       + sgA2[t]       + bih[t];
        float gh_r = sgB[t]       + sgB2[t]       + bhh[t];
        float gi_z = sgA[128 + t] + sgA2[128 + t] + bih[128 + t];
        float gh_z = sgB[128 + t] + sgB2[128 + t] + bhh[128 + t];
        float gi_n = sgA[256 + t] + sgA2[256 + t] + bih[256 + t];
        float gh_n = sgB[256 + t] + sgB2[256 + t] + bhh[256 + t];
        float r = sigmoidf_(gi_r + gh_r);
        float z = sigmoidf_(gi_z + gh_z);
        float nn = tanhf(gi_n + r * gh_n);
        hg = (1.0f - z) * nn + z * hs[t];
        hgs[t] = hg;
    }
    {
        float v = (t < 128) ? hg : 0.0f;
        float m = blocksum384(v, red) * (1.0f / 128.0f);
        float dx = (t < 128) ? (hg - m) : 0.0f;
        float var = blocksum384(dx * dx, red) * (1.0f / 128.0f);
        if (t < 128) ffs[t] = dx * rsqrtf(var + 1e-5f) * g_ff[t] + be_ff[t];
    }
    __syncthreads();

    // phase D: FF1 (relu(ffs @ W1T + b1)), 256 threads: 32 quads x 8 d-parts
    if (t < 256) {
        int q = t & 31, p = t >> 5;
        float4 acc = make_float4(0.f, 0.f, 0.f, 0.f);
        #pragma unroll
        for (int i = 0; i < 16; i++) {
            int d = p * 16 + i;
            float4 w4 = *(const float4*)(g_W1T + d * Dc + q * 4);
            float xd = ffs[d];
            acc.x += xd * w4.x; acc.y += xd * w4.y;
            acc.z += xd * w4.z; acc.w += xd * w4.w;
        }
        *(float4*)(&fpart[p][q * 4]) = acc;
    }
    __syncthreads();
    if (t < 128) {
        float sum = b1[t];
        #pragma unroll
        for (int p = 0; p < 8; p++) sum += fpart[p][t];
        hid[t] = fmaxf(sum, 0.0f);
    }
    __syncthreads();

    // phase E: FF2
    if (t < 256) {
        int q = t & 31, p = t >> 5;
        float4 acc = make_float4(0.f, 0.f, 0.f, 0.f);
        #pragma unroll
        for (int i = 0; i < 16; i++) {
            int d = p * 16 + i;
            float4 w4 = *(const float4*)(g_W2T + d * Dc + q * 4);
            float xd = hid[d];
            acc.x += xd * w4.x; acc.y += xd * w4.y;
            acc.z += xd * w4.z; acc.w += xd * w4.w;
        }
        *(float4*)(&fpart[p][q * 4]) = acc;
    }
    __syncthreads();
    float snew = 0.0f;
    if (t < 128) {
        float sum = b2[t];
        #pragma unroll
        for (int p = 0; p < 8; p++) sum += fpart[p][t];
        snew = hgs[t] + sum;
        g_slots[bs * Dc + t] = snew;
        if (emit) {
            int b = bs >> 3, s = bs & 7;
            out_slots[(((size_t)b * NFc + f) * Sc + s) * Dc + t] = snew;
        }
    }

    // phase F: next q = LN(snew; g_sl) @ WqT + bq
    {
        float v = (t < 128) ? snew : 0.0f;
        float m = blocksum384(v, red) * (1.0f / 128.0f);
        float dx = (t < 128) ? (snew - m) : 0.0f;
        float var = blocksum384(dx * dx, red) * (1.0f / 128.0f);
        if (t < 128) ln2s[t] = dx * rsqrtf(var + 1e-5f) * g_sl[t] + be_sl[t];
    }
    __syncthreads();
    if (t < 256) {
        int q = t & 31, p = t >> 5;
        float4 acc = make_float4(0.f, 0.f, 0.f, 0.f);
        #pragma unroll
        for (int i = 0; i < 16; i++) {
            int d = p * 16 + i;
            float4 w4 = *(const float4*)(g_WqT + d * Dc + q * 4);
            float xd = ln2s[d];
            acc.x += xd * w4.x; acc.y += xd * w4.y;
            acc.z += xd * w4.z; acc.w += xd * w4.w;
        }
        *(float4*)(&fpart[p][q * 4]) = acc;
    }
    __syncthreads();
    if (t < 128) {
        float sum = bq[t];
        #pragma unroll
        for (int p = 0; p < 8; p++) sum += fpart[p][t];
        g_q[bs * Dc + t] = sum;
    }
}

// ---------------- launch ----------------
extern "C" void kernel_launch(void* const* d_in, const int* in_sizes, int n_in,
                              void* d_out, int out_size) {
    const float* inputs     = (const float*)d_in[0];
    const float* slots_init = (const float*)d_in[1];
    const float* Wq  = (const float*)d_in[2];
    const float* bq  = (const float*)d_in[3];
    const float* Wk  = (const float*)d_in[4];
    const float* bk  = (const float*)d_in[5];
    const float* Wv  = (const float*)d_in[6];
    const float* bv  = (const float*)d_in[7];
    const float* W1  = (const float*)d_in[8];
    const float* b1  = (const float*)d_in[9];
    const float* W2  = (const float*)d_in[10];
    const float* b2  = (const float*)d_in[11];
    const float* Wih = (const float*)d_in[12];
    const float* Whh = (const float*)d_in[13];
    const float* bih = (const float*)d_in[14];
    const float* bhh = (const float*)d_in[15];
    const float* g_in  = (const float*)d_in[16];
    const float* be_in = (const float*)d_in[17];
    const float* g_sl  = (const float*)d_in[18];
    const float* be_sl = (const float*)d_in[19];
    const float* g_ff  = (const float*)d_in[20];
    const float* be_ff = (const float*)d_in[21];

    float* out = (float*)d_out;
    float* out_slots = out;                                 // [B,NF,S,D]
    float* out_attn  = out + (size_t)Bc * NFc * Sc * Dc;    // [B,NF,S,N]

    cudaFuncSetAttribute(gemm2_kernel, cudaFuncAttributeMaxDynamicSharedMemorySize, GEMM2_SMEM);

    prep_kernel<<<192, 256>>>(Wq, W1, W2, Wih, Whh, Wk, Wv);
    gemm2_kernel<<<Mtot / 128 / NTILES, 256, GEMM2_SMEM>>>(inputs, g_in, be_in, bk, bv);
    init_kernel<<<BSc, Dc>>>(slots_init, g_sl, be_sl, bq);

    for (int step = 0; step < NFc + 1; step++) {
        int f = (step == 0) ? 0 : step - 1;
        int emit = (step > 0) ? 1 : 0;
        stepB_kernel<<<dim3(NCHUNK, Bc), 256>>>(f, emit, out_attn);
        stepC_kernel<<<BSc, 384>>>(f, emit, out_slots,
                                   bih, bhh, g_ff, be_ff, b1, b2, g_sl, be_sl, bq);
    }
}

// round 7
// speedup vs baseline: 2.8775x; 1.0635x over previous
#include <cuda_runtime.h>
#include <cuda_bf16.h>
#include <cstdint>

#define Bc   16
#define NFc  16
#define Nc   1024
#define Dc   128
#define Sc   8
#define Hc   128
#define BSc  (Bc*Sc)          // 128
#define Mtot (Bc*NFc*Nc)      // 262144
#define NCHUNK 16
#define CHTOK  64             // tokens per chunk
#define SCALEc 0.08838834764831845f
#define EPSc   1e-8f

// ---------------- device scratch (no allocations allowed) ----------------
__device__ float g_K[Bc*NFc*Nc*Dc];          // 134 MB
__device__ float g_V[Bc*NFc*Nc*Dc];          // 134 MB
__device__ __nv_bfloat16 g_Wkvhi[2*Dc*Dc];   // [0]=Wk, [1]=Wv, layout [n][k]
__device__ __nv_bfloat16 g_Wkvlo[2*Dc*Dc];
__device__ float g_q[BSc*Dc];
__device__ float g_slots[BSc*Dc];
__device__ float g_Upart[NCHUNK*BSc*Dc];     // 1 MB
__device__ float g_rspart[NCHUNK*BSc];
__device__ float g_WqT[Dc*Dc];
__device__ float g_W1T[Dc*Hc];
__device__ float g_W2T[Hc*Dc];
__device__ float g_WihT[Dc*3*Dc];
__device__ float g_WhhT[Dc*3*Dc];

// ---------------- helpers ----------------
__device__ __forceinline__ float blocksum128(float v, float* red) {
    #pragma unroll
    for (int o = 16; o; o >>= 1) v += __shfl_xor_sync(0xffffffffu, v, o);
    int t = threadIdx.x;
    if ((t & 31) == 0) red[t >> 5] = v;
    __syncthreads();
    float r = red[0] + red[1] + red[2] + red[3];
    __syncthreads();
    return r;
}
// 384-thread variant; callers pass 0 for t>=128
__device__ __forceinline__ float blocksum384(float v, float* red) {
    #pragma unroll
    for (int o = 16; o; o >>= 1) v += __shfl_xor_sync(0xffffffffu, v, o);
    int t = threadIdx.x;
    if ((t & 31) == 0) red[t >> 5] = v;
    __syncthreads();
    float r = 0.0f;
    #pragma unroll
    for (int i = 0; i < 12; i++) r += red[i];
    __syncthreads();
    return r;
}
__device__ __forceinline__ float sigmoidf_(float x) { return 1.0f / (1.0f + expf(-x)); }

__device__ __forceinline__ void mma16816(float* c, const uint32_t* a, const uint32_t* b) {
    asm volatile(
        "mma.sync.aligned.m16n8k16.row.col.f32.bf16.bf16.f32 "
        "{%0,%1,%2,%3}, {%4,%5,%6,%7}, {%8,%9}, {%0,%1,%2,%3};"
        : "+f"(c[0]), "+f"(c[1]), "+f"(c[2]), "+f"(c[3])
        : "r"(a[0]), "r"(a[1]), "r"(a[2]), "r"(a[3]), "r"(b[0]), "r"(b[1]));
}
__device__ __forceinline__ void ldsm_x4(uint32_t* r, const void* p) {
    uint32_t addr = (uint32_t)__cvta_generic_to_shared(p);
    asm volatile("ldmatrix.sync.aligned.m8n8.x4.shared.b16 {%0,%1,%2,%3}, [%4];"
        : "=r"(r[0]), "=r"(r[1]), "=r"(r[2]), "=r"(r[3]) : "r"(addr));
}

// ---------------- prep: transposes + bf16 weight splits ------------------
__global__ void prep_kernel(const float* __restrict__ Wq, const float* __restrict__ W1,
                            const float* __restrict__ W2, const float* __restrict__ Wih,
                            const float* __restrict__ Whh,
                            const float* __restrict__ Wk, const float* __restrict__ Wv) {
    int idx = blockIdx.x * 256 + threadIdx.x;
    if (idx < Dc * Dc) {
        int r = idx >> 7, c = idx & 127;
        g_WqT[c * Dc + r] = Wq[idx];
        g_W1T[c * Dc + r] = W1[idx];
        g_W2T[c * Dc + r] = W2[idx];
        float wkv = Wk[idx];
        __nv_bfloat16 h = __float2bfloat16_rn(wkv);
        g_Wkvhi[idx] = h;
        g_Wkvlo[idx] = __float2bfloat16_rn(wkv - __bfloat162float(h));
        wkv = Wv[idx];
        h = __float2bfloat16_rn(wkv);
        g_Wkvhi[Dc*Dc + idx] = h;
        g_Wkvlo[Dc*Dc + idx] = __float2bfloat16_rn(wkv - __bfloat162float(h));
    }
    if (idx < 3 * Dc * Dc) {
        int j = idx >> 7, d = idx & 127;
        g_WihT[d * 384 + j] = Wih[idx];
        g_WhhT[d * 384 + j] = Whh[idx];
    }
}

// ---------------- gemm2: fused LN + split-bf16 mma for K and V ----------
// grid Mtot/128/NTILES blocks, 256 threads (8 warps, 4x2 warp tiling)
#define GST 136
#define NTILES 8
#define GEMM2_SMEM (6 * 128 * GST * 2)     // 208896 B
__global__ void __launch_bounds__(256, 1) gemm2_kernel(
        const float* __restrict__ x,
        const float* __restrict__ g_in, const float* __restrict__ be_in,
        const float* __restrict__ bk, const float* __restrict__ bv) {
    extern __shared__ __nv_bfloat16 sm[];
    __nv_bfloat16* xhi = sm;
    __nv_bfloat16* xlo = xhi + 128 * GST;
    __nv_bfloat16* wts = xlo + 128 * GST;  // [4][128][GST]: Khi, Klo, Vhi, Vlo

    const int t = threadIdx.x;
    const int lane = t & 31, w = t >> 5;

    // load 4 weight tiles (32 uint4 per thread)
    #pragma unroll
    for (int i = 0; i < 32; i++) {
        int l = t + i * 256;
        int tile = l >> 11;
        int rem = l & 2047;
        int r = rem >> 4, kc = (rem & 15) * 8;
        const __nv_bfloat16* src =
            (tile == 0) ? g_Wkvhi : (tile == 1) ? g_Wkvlo :
            (tile == 2) ? (g_Wkvhi + Dc*Dc) : (g_Wkvlo + Dc*Dc);
        *(uint4*)(wts + tile * 128 * GST + r * GST + kc) = *(const uint4*)(src + r * Dc + kc);
    }

    float4 gg = ((const float4*)g_in)[lane];
    float4 bb = ((const float4*)be_in)[lane];

    const int wr = (w >> 1) * 32;
    const int wc = (w & 1) * 64;
    const int g = lane >> 2, tg = lane & 3;

    for (int it = 0; it < NTILES; it++) {
        __syncthreads();   // weights ready (it=0) / prior mma reads done
        const size_t m0 = ((size_t)blockIdx.x * NTILES + it) * 128;

        // LN 16 rows per warp -> split bf16 into xhi/xlo
        for (int r = w; r < 128; r += 8) {
            float4 v = ((const float4*)(x + (m0 + r) * Dc))[lane];
            float s = v.x + v.y + v.z + v.w;
            #pragma unroll
            for (int o = 16; o; o >>= 1) s += __shfl_xor_sync(0xffffffffu, s, o);
            float m = s * (1.0f / 128.0f);
            float d0 = v.x - m, d1 = v.y - m, d2 = v.z - m, d3 = v.w - m;
            float ss = d0*d0 + d1*d1 + d2*d2 + d3*d3;
            #pragma unroll
            for (int o = 16; o; o >>= 1) ss += __shfl_xor_sync(0xffffffffu, ss, o);
            float inv = rsqrtf(ss * (1.0f / 128.0f) + 1e-5f);
            float y0 = d0*inv*gg.x + bb.x, y1 = d1*inv*gg.y + bb.y;
            float y2 = d2*inv*gg.z + bb.z, y3 = d3*inv*gg.w + bb.w;
            __nv_bfloat16 h0 = __float2bfloat16_rn(y0), h1 = __float2bfloat16_rn(y1);
            __nv_bfloat16 h2 = __float2bfloat16_rn(y2), h3 = __float2bfloat16_rn(y3);
            __nv_bfloat16 l0 = __float2bfloat16_rn(y0 - __bfloat162float(h0));
            __nv_bfloat16 l1 = __float2bfloat16_rn(y1 - __bfloat162float(h1));
            __nv_bfloat16 l2 = __float2bfloat16_rn(y2 - __bfloat162float(h2));
            __nv_bfloat16 l3 = __float2bfloat16_rn(y3 - __bfloat162float(h3));
            ushort4 ph = make_ushort4(*(unsigned short*)&h0, *(unsigned short*)&h1,
                                      *(unsigned short*)&h2, *(unsigned short*)&h3);
            ushort4 pl = make_ushort4(*(unsigned short*)&l0, *(unsigned short*)&l1,
                                      *(unsigned short*)&l2, *(unsigned short*)&l3);
            *(ushort4*)(xhi + r * GST + lane * 4) = ph;
            *(ushort4*)(xlo + r * GST + lane * 4) = pl;
        }
        __syncthreads();

        #pragma unroll
        for (int y = 0; y < 2; y++) {
            const __nv_bfloat16* whi = wts + (y * 2 + 0) * 128 * GST;
            const __nv_bfloat16* wlo = wts + (y * 2 + 1) * 128 * GST;
            float acc[2][8][4];
            #pragma unroll
            for (int mi = 0; mi < 2; mi++)
                #pragma unroll
                for (int ni = 0; ni < 8; ni++)
                    #pragma unroll
                    for (int j = 0; j < 4; j++) acc[mi][ni][j] = 0.0f;

            #pragma unroll
            for (int p = 0; p < 3; p++) {
                const __nv_bfloat16* As = (p == 2) ? xlo : xhi;
                const __nv_bfloat16* Bs = (p == 1) ? wlo : whi;
                #pragma unroll
                for (int kk = 0; kk < 8; kk++) {
                    const int kb = kk * 16;
                    uint32_t afr[2][4], bfr[8][2];
                    #pragma unroll
                    for (int mi = 0; mi < 2; mi++) {
                        int row = wr + mi * 16 + (lane & 15);
                        int kc = kb + (lane >> 4) * 8;
                        ldsm_x4(afr[mi], As + row * GST + kc);
                    }
                    #pragma unroll
                    for (int nj = 0; nj < 4; nj++) {
                        int n = wc + nj * 16 + (lane & 7) + ((lane >> 4) << 3);
                        int kc = kb + ((lane >> 3) & 1) * 8;
                        uint32_t b4[4];
                        ldsm_x4(b4, Bs + n * GST + kc);
                        bfr[2*nj][0] = b4[0]; bfr[2*nj][1] = b4[1];
                        bfr[2*nj+1][0] = b4[2]; bfr[2*nj+1][1] = b4[3];
                    }
                    #pragma unroll
                    for (int mi = 0; mi < 2; mi++)
                        #pragma unroll
                        for (int ni = 0; ni < 8; ni++)
                            mma16816(acc[mi][ni], afr[mi], bfr[ni]);
                }
            }

            float* outp = y ? g_V : g_K;
            const float* bias = y ? bv : bk;
            #pragma unroll
            for (int mi = 0; mi < 2; mi++) {
                #pragma unroll
                for (int ni = 0; ni < 8; ni++) {
                    size_t r0 = m0 + wr + mi * 16 + g;
                    int c0 = wc + ni * 8 + tg * 2;
                    float b0 = bias[c0], b1 = bias[c0 + 1];
                    float2 v0 = make_float2(acc[mi][ni][0] + b0, acc[mi][ni][1] + b1);
                    float2 v1 = make_float2(acc[mi][ni][2] + b0, acc[mi][ni][3] + b1);
                    *(float2*)(outp + r0 * Dc + c0) = v0;
                    *(float2*)(outp + (r0 + 8) * Dc + c0) = v1;
                }
            }
        }
    }
}

// ---------------- init: slots = broadcast(slots_init); q0 ----------------
__global__ void init_kernel(const float* __restrict__ slots_init,
                            const float* __restrict__ g_sl, const float* __restrict__ be_sl,
                            const float* __restrict__ bq) {
    __shared__ float lnv[Dc];
    __shared__ float red[4];
    const int t = threadIdx.x;
    const int bs = blockIdx.x;           // b*8 + s
    const int s = bs & 7;
    float v = slots_init[s * Dc + t];
    g_slots[bs * Dc + t] = v;
    float m = blocksum128(v, red) * (1.0f / 128.0f);
    float dx = v - m;
    float var = blocksum128(dx * dx, red) * (1.0f / 128.0f);
    float l = dx * rsqrtf(var + 1e-5f) * g_sl[t] + be_sl[t];
    lnv[t] = l;
    __syncthreads();
    float qa = bq[t];
    #pragma unroll 4
    for (int d = 0; d < 128; d++) qa += lnv[d] * g_WqT[d * Dc + t];
    g_q[bs * Dc + t] = qa;
}

// ---------------- stepB: dots, softmax over slots, partial updates ------
// grid (16 chunks of 64 tokens, 16 batches), 256 threads, dynamic smem
#define KVST 132                         // floats per row (33 float4s, conflict-free/broadcast)
#define ASTB 65
#define B_SMEM ((CHTOK*KVST*2 + Sc*KVST + Sc*ASTB) * 4)
__global__ void __launch_bounds__(256) stepB_kernel(int f, int emit, float* __restrict__ out_attn) {
    extern __shared__ float smb[];
    float* ks = smb;                     // [64][KVST]
    float* vs = ks + CHTOK * KVST;       // [64][KVST]
    float* qs = vs + CHTOK * KVST;       // [8][KVST]
    float* as = qs + Sc * KVST;          // [8][65]

    const int t = threadIdx.x;
    const int chunk = blockIdx.x;        // 64-token chunk
    const int b = blockIdx.y;
    const int bf = b * NFc + f;
    const float* kg = g_K + (size_t)bf * Nc * Dc + (size_t)chunk * CHTOK * Dc;
    const float* vg = g_V + (size_t)bf * Nc * Dc + (size_t)chunk * CHTOK * Dc;

    // stage K,V: 64 rows x 32 quads = 2048 quads each; 8 per thread per array
    #pragma unroll
    for (int i = 0; i < 8; i++) {
        int l = t + i * 256;
        int r = l >> 5, dq = (l & 31) * 4;
        *(float4*)(ks + r * KVST + dq) = *(const float4*)(kg + r * Dc + dq);
        *(float4*)(vs + r * KVST + dq) = *(const float4*)(vg + r * Dc + dq);
    }
    // stage q: 256 quads, 1 per thread
    {
        int s = t >> 5, dq = (t & 31) * 4;
        *(float4*)(qs + s * KVST + dq) = *(const float4*)(g_q + b * Sc * Dc + s * Dc + dq);
    }
    __syncthreads();

    // dots: thread -> (tokens tt0, tt0+32; slot s); q4 reused for both
    const int tt0 = t >> 3;              // 0..31
    const int s = t & 7;
    float dot0 = 0.0f, dot1 = 0.0f;
    const float* qrow = qs + s * KVST;
    const float* krow0 = ks + tt0 * KVST;
    const float* krow1 = krow0 + 32 * KVST;
    #pragma unroll 8
    for (int j = 0; j < 32; j++) {
        float4 q4 = *(const float4*)(qrow + j * 4);
        float4 k0 = *(const float4*)(krow0 + j * 4);
        float4 k1 = *(const float4*)(krow1 + j * 4);
        dot0 += q4.x*k0.x + q4.y*k0.y + q4.z*k0.z + q4.w*k0.w;
        dot1 += q4.x*k1.x + q4.y*k1.y + q4.z*k1.z + q4.w*k1.w;
    }
    dot0 *= SCALEc; dot1 *= SCALEc;
    // softmax over 8 slots (8 consecutive lanes share a token)
    float mx0 = dot0, mx1 = dot1;
    #pragma unroll
    for (int o = 4; o; o >>= 1) {
        mx0 = fmaxf(mx0, __shfl_xor_sync(0xffffffffu, mx0, o));
        mx1 = fmaxf(mx1, __shfl_xor_sync(0xffffffffu, mx1, o));
    }
    float e0 = expf(dot0 - mx0), e1 = expf(dot1 - mx1);
    float s0 = e0, s1 = e1;
    #pragma unroll
    for (int o = 4; o; o >>= 1) {
        s0 += __shfl_xor_sync(0xffffffffu, s0, o);
        s1 += __shfl_xor_sync(0xffffffffu, s1, o);
    }
    float a0 = e0 / s0 + EPSc;
    float a1 = e1 / s1 + EPSc;
    as[s * ASTB + tt0] = a0;
    as[s * ASTB + tt0 + 32] = a1;
    __syncthreads();

    // coalesced attn emit via smem staging (512 floats, 2 per thread)
    if (emit) {
        float* oa = out_attn + (size_t)bf * Sc * Nc + chunk * CHTOK;
        #pragma unroll
        for (int i = 0; i < 2; i++) {
            int idx = t + i * 256;
            int s3 = idx >> 6, n3 = idx & 63;
            oa[(size_t)s3 * Nc + n3] = as[s3 * ASTB + n3];
        }
    }

    // rowsum partials: warp w handles slot w
    const int w = t >> 5, lane = t & 31;
    {
        float rs = as[w * ASTB + lane] + as[w * ASTB + lane + 32];
        #pragma unroll
        for (int o = 16; o; o >>= 1) rs += __shfl_xor_sync(0xffffffffu, rs, o);
        if (lane == 0) g_rspart[chunk * BSc + b * Sc + w] = rs;
    }

    // partial updates: warp w = slot w; lane owns d-quad
    {
        float4 up = make_float4(0.f, 0.f, 0.f, 0.f);
        const float* arow = as + w * ASTB;
        #pragma unroll 8
        for (int n = 0; n < CHTOK; n++) {
            float a = arow[n];                       // warp-broadcast
            float4 v4 = *(const float4*)(vs + n * KVST + lane * 4);
            up.x += a * v4.x; up.y += a * v4.y;
            up.z += a * v4.z; up.w += a * v4.w;
        }
        *(float4*)(g_Upart + (size_t)(chunk * BSc + b * Sc + w) * Dc + lane * 4) = up;
    }
}

// ---------------- stepC: finalize updates, GRU, FF, next q --------------
// grid 128 blocks (one per b*8+s), 384 threads
__global__ void __launch_bounds__(384) stepC_kernel(int f, int emit, float* __restrict__ out_slots,
                             const float* __restrict__ bih, const float* __restrict__ bhh,
                             const float* __restrict__ g_ff, const float* __restrict__ be_ff,
                             const float* __restrict__ b1, const float* __restrict__ b2,
                             const float* __restrict__ g_sl, const float* __restrict__ be_sl,
                             const float* __restrict__ bq) {
    __shared__ float us[Dc], hs[Dc], hgs[Dc], ffs[Dc], hid[Dc], ln2s[Dc];
    __shared__ float sgA[384], sgB[384], sgA2[384], sgB2[384];
    __shared__ float fpart[8][Dc];
    __shared__ float upp[8][Dc];
    __shared__ float rsp[16];
    __shared__ float red[12];

    const int t = threadIdx.x;
    const int bs = blockIdx.x;

    // phase A: finalize updates (float4 loads, 2 chunks per thread)
    if (t < 256) {
        int cg = t >> 5;                 // 0..7
        int dq = (t & 31) * 4;
        float4 ua = *(const float4*)(g_Upart + (size_t)(cg * BSc + bs) * Dc + dq);
        float4 ub = *(const float4*)(g_Upart + (size_t)((cg + 8) * BSc + bs) * Dc + dq);
        ua.x += ub.x; ua.y += ub.y; ua.z += ub.z; ua.w += ub.w;
        *(float4*)(&upp[cg][dq]) = ua;
    }
    if (t < 16) rsp[t] = g_rspart[t * BSc + bs];
    __syncthreads();
    if (t < 128) {
        float usum = 0.0f;
        #pragma unroll
        for (int c = 0; c < 8; c++) usum += upp[c][t];
        float rsum = 0.0f;
        #pragma unroll
        for (int c = 0; c < 16; c++) rsum += rsp[c];
        us[t] = usum / rsum;
        hs[t] = g_slots[bs * Dc + t];
    }
    __syncthreads();

    // phase B: GRU gate GEMVs, 4 groups x 96 threads, float4 outputs
    {
        int grp = t / 96;               // 0: gi d<64, 1: gh d<64, 2: gi d>=64, 3: gh d>=64
        int q = t - grp * 96;           // 0..95 -> output quad j=4q
        const float* W = (grp & 1) ? g_WhhT : g_WihT;
        const float* xv = (grp & 1) ? hs : us;
        int d0 = (grp >> 1) * 64;
        float4 acc = make_float4(0.f, 0.f, 0.f, 0.f);
        #pragma unroll 16
        for (int i = 0; i < 64; i++) {
            int d = d0 + i;
            float4 w4 = *(const float4*)(W + d * 384 + q * 4);
            float xd = xv[d];
            acc.x += xd * w4.x; acc.y += xd * w4.y;
            acc.z += xd * w4.z; acc.w += xd * w4.w;
        }
        float* dst = (grp == 0) ? sgA : (grp == 1) ? sgB : (grp == 2) ? sgA2 : sgB2;
        *(float4*)(dst + q * 4) = acc;
    }
    __syncthreads();

    // phase C: gates + GRU + LN for FF
    float hg = 0.0f;
    if (t < 128) {
        float gi_r = sgA[t]       + sgA2[t]       + bih[t];
        float gh_r = sgB[t]       + sgB2[t]       + bhh[t];
        float gi_z = sgA[128 + t] + sgA2[128 + t] + bih[128 + t];
        float gh_z = sgB[128 + t] + sgB2[128 + t] + bhh[128 + t];
        float gi_n = sgA[256 + t] + sgA2[256 + t] + bih[256 + t];
        float gh_n = sgB[256 + t] + sgB2[256 + t] + bhh[256 + t];
        float r = sigmoidf_(gi_r + gh_r);
        float z = sigmoidf_(gi_z + gh_z);
        float nn = tanhf(gi_n + r * gh_n);
        hg = (1.0f - z) * nn + z * hs[t];
        hgs[t] = hg;
    }
    {
        float v = (t < 128) ? hg : 0.0f;
        float m = blocksum384(v, red) * (1.0f / 128.0f);
        float dx = (t < 128) ? (hg - m) : 0.0f;
        float var = blocksum384(dx * dx, red) * (1.0f / 128.0f);
        if (t < 128) ffs[t] = dx * rsqrtf(var + 1e-5f) * g_ff[t] + be_ff[t];
    }
    __syncthreads();

    // phase D: FF1 (relu(ffs @ W1T + b1)), 256 threads: 32 quads x 8 d-parts
    if (t < 256) {
        int q = t & 31, p = t >> 5;
        float4 acc = make_float4(0.f, 0.f, 0.f, 0.f);
        #pragma unroll
        for (int i = 0; i < 16; i++) {
            int d = p * 16 + i;
            float4 w4 = *(const float4*)(g_W1T + d * Dc + q * 4);
            float xd = ffs[d];
            acc.x += xd * w4.x; acc.y += xd * w4.y;
            acc.z += xd * w4.z; acc.w += xd * w4.w;
        }
        *(float4*)(&fpart[p][q * 4]) = acc;
    }
    __syncthreads();
    if (t < 128) {
        float sum = b1[t];
        #pragma unroll
        for (int p = 0; p < 8; p++) sum += fpart[p][t];
        hid[t] = fmaxf(sum, 0.0f);
    }
    __syncthreads();

    // phase E: FF2
    if (t < 256) {
        int q = t & 31, p = t >> 5;
        float4 acc = make_float4(0.f, 0.f, 0.f, 0.f);
        #pragma unroll
        for (int i = 0; i < 16; i++) {
            int d = p * 16 + i;
            float4 w4 = *(const float4*)(g_W2T + d * Dc + q * 4);
            float xd = hid[d];
            acc.x += xd * w4.x; acc.y += xd * w4.y;
            acc.z += xd * w4.z; acc.w += xd * w4.w;
        }
        *(float4*)(&fpart[p][q * 4]) = acc;
    }
    __syncthreads();
    float snew = 0.0f;
    if (t < 128) {
        float sum = b2[t];
        #pragma unroll
        for (int p = 0; p < 8; p++) sum += fpart[p][t];
        snew = hgs[t] + sum;
        g_slots[bs * Dc + t] = snew;
        if (emit) {
            int b = bs >> 3, s = bs & 7;
            out_slots[(((size_t)b * NFc + f) * Sc + s) * Dc + t] = snew;
        }
    }

    // phase F: next q = LN(snew; g_sl) @ WqT + bq
    {
        float v = (t < 128) ? snew : 0.0f;
        float m = blocksum384(v, red) * (1.0f / 128.0f);
        float dx = (t < 128) ? (snew - m) : 0.0f;
        float var = blocksum384(dx * dx, red) * (1.0f / 128.0f);
        if (t < 128) ln2s[t] = dx * rsqrtf(var + 1e-5f) * g_sl[t] + be_sl[t];
    }
    __syncthreads();
    if (t < 256) {
        int q = t & 31, p = t >> 5;
        float4 acc = make_float4(0.f, 0.f, 0.f, 0.f);
        #pragma unroll
        for (int i = 0; i < 16; i++) {
            int d = p * 16 + i;
            float4 w4 = *(const float4*)(g_WqT + d * Dc + q * 4);
            float xd = ln2s[d];
            acc.x += xd * w4.x; acc.y += xd * w4.y;
            acc.z += xd * w4.z; acc.w += xd * w4.w;
        }
        *(float4*)(&fpart[p][q * 4]) = acc;
    }
    __syncthreads();
    if (t < 128) {
        float sum = bq[t];
        #pragma unroll
        for (int p = 0; p < 8; p++) sum += fpart[p][t];
        g_q[bs * Dc + t] = sum;
    }
}

// ---------------- launch ----------------
extern "C" void kernel_launch(void* const* d_in, const int* in_sizes, int n_in,
                              void* d_out, int out_size) {
    const float* inputs     = (const float*)d_in[0];
    const float* slots_init = (const float*)d_in[1];
    const float* Wq  = (const float*)d_in[2];
    const float* bq  = (const float*)d_in[3];
    const float* Wk  = (const float*)d_in[4];
    const float* bk  = (const float*)d_in[5];
    const float* Wv  = (const float*)d_in[6];
    const float* bv  = (const float*)d_in[7];
    const float* W1  = (const float*)d_in[8];
    const float* b1  = (const float*)d_in[9];
    const float* W2  = (const float*)d_in[10];
    const float* b2  = (const float*)d_in[11];
    const float* Wih = (const float*)d_in[12];
    const float* Whh = (const float*)d_in[13];
    const float* bih = (const float*)d_in[14];
    const float* bhh = (const float*)d_in[15];
    const float* g_in  = (const float*)d_in[16];
    const float* be_in = (const float*)d_in[17];
    const float* g_sl  = (const float*)d_in[18];
    const float* be_sl = (const float*)d_in[19];
    const float* g_ff  = (const float*)d_in[20];
    const float* be_ff = (const float*)d_in[21];

    float* out = (float*)d_out;
    float* out_slots = out;                                 // [B,NF,S,D]
    float* out_attn  = out + (size_t)Bc * NFc * Sc * Dc;    // [B,NF,S,N]

    cudaFuncSetAttribute(gemm2_kernel, cudaFuncAttributeMaxDynamicSharedMemorySize, GEMM2_SMEM);
    cudaFuncSetAttribute(stepB_kernel, cudaFuncAttributeMaxDynamicSharedMemorySize, B_SMEM);

    prep_kernel<<<192, 256>>>(Wq, W1, W2, Wih, Whh, Wk, Wv);
    gemm2_kernel<<<Mtot / 128 / NTILES, 256, GEMM2_SMEM>>>(inputs, g_in, be_in, bk, bv);
    init_kernel<<<BSc, Dc>>>(slots_init, g_sl, be_sl, bq);

    for (int step = 0; step < NFc + 1; step++) {
        int f = (step == 0) ? 0 : step - 1;
        int emit = (step > 0) ? 1 : 0;
        stepB_kernel<<<dim3(NCHUNK, Bc), 256, B_SMEM>>>(f, emit, out_attn);
        stepC_kernel<<<BSc, 384>>>(f, emit, out_slots,
                                   bih, bhh, g_ff, be_ff, b1, b2, g_sl, be_sl, bq);
    }
}

// round 8
// speedup vs baseline: 4.7411x; 1.6476x over previous
#include <cuda_runtime.h>
#include <cstdint>

#define Bc   16
#define NFc  16
#define Nc   1024
#define Dc   128
#define Sc   8
#define Hc   128
#define BSc  (Bc*Sc)          // 128
#define NCHUNK 16
#define CHTOK  64             // tokens per chunk
#define SCALEc 0.08838834764831845f
#define EPSc   1e-8f

// ---------------- device scratch ----------------
__device__ float g_qt[BSc*Dc];        // per-(b,s) transformed query (Wk^T q)
__device__ float g_qb[BSc];           // per-(b,s) scalar q.bk
__device__ float g_slots[BSc*Dc];
__device__ float g_Yapart[NCHUNK*BSc*Dc];   // 0.5 MB: per-chunk  sum_n a*xn
__device__ float g_rspart[NCHUNK*BSc];
__device__ float g_WcT[Dc*3*Dc];      // (Wih @ Wv)^T : [e][j=0..383]
__device__ float g_bc[3*Dc];          // Wih @ bv
__device__ float g_WhhT[Dc*3*Dc];
__device__ float g_W1T[Dc*Hc];
__device__ float g_W2T[Hc*Dc];
__device__ float g_MT[Dc*Dc];         // (Wk^T Wq)^T rows: MT[e][d]
__device__ float g_qtb[Dc];           // Wk^T bq
__device__ float g_qbv[Dc];           // Wq^T bk
__device__ float g_qbb[1];            // bq . bk

// ---------------- helpers ----------------
__device__ __forceinline__ float blocksum128(float v, float* red) {
    #pragma unroll
    for (int o = 16; o; o >>= 1) v += __shfl_xor_sync(0xffffffffu, v, o);
    int t = threadIdx.x;
    if ((t & 31) == 0) red[t >> 5] = v;
    __syncthreads();
    float r = red[0] + red[1] + red[2] + red[3];
    __syncthreads();
    return r;
}
__device__ __forceinline__ float blocksum384(float v, float* red) {
    #pragma unroll
    for (int o = 16; o; o >>= 1) v += __shfl_xor_sync(0xffffffffu, v, o);
    int t = threadIdx.x;
    if ((t & 31) == 0) red[t >> 5] = v;
    __syncthreads();
    float r = 0.0f;
    #pragma unroll
    for (int i = 0; i < 12; i++) r += red[i];
    __syncthreads();
    return r;
}
__device__ __forceinline__ float sigmoidf_(float x) { return 1.0f / (1.0f + expf(-x)); }

// ---------------- prepT: transposes + bias vectors ----------------
// grid 193 blocks x 256 threads
__global__ void prepT_kernel(const float* __restrict__ Wq, const float* __restrict__ bq,
                             const float* __restrict__ Wk, const float* __restrict__ bk,
                             const float* __restrict__ W1, const float* __restrict__ W2,
                             const float* __restrict__ Wih, const float* __restrict__ Whh,
                             const float* __restrict__ bv) {
    int blk = blockIdx.x;
    int t = threadIdx.x;
    if (blk < 192) {
        int idx = blk * 256 + t;          // < 49152
        int j = idx >> 7, d = idx & 127;
        g_WhhT[d * 384 + j] = Whh[idx];
        if (idx < Dc * Dc) {
            int r = idx >> 7, c = idx & 127;
            g_W1T[c * Dc + r] = W1[idx];
            g_W2T[c * Dc + r] = W2[idx];
        }
    } else {
        // vectors
        if (t < 128) {
            float aq = 0.0f, ab = 0.0f;
            for (int j = 0; j < 128; j++) {
                aq += Wq[j * 128 + t] * bk[j];   // qbv
                ab += Wk[j * 128 + t] * bq[j];   // qtb
            }
            g_qbv[t] = aq;
            g_qtb[t] = ab;
            if (t == 0) {
                float s = 0.0f;
                for (int j = 0; j < 128; j++) s += bq[j] * bk[j];
                g_qbb[0] = s;
            }
        }
        // bc[j] = sum_d Wih[j][d]*bv[d]
        for (int j = t; j < 384; j += 256) {
            float s = 0.0f;
            for (int d = 0; d < 128; d++) s += Wih[j * 128 + d] * bv[d];
            g_bc[j] = s;
        }
    }
}

// ---------------- prepWc: WcT[e][j] = sum_d Wih[j][d] Wv[d][e] -----------
// grid 384 blocks (j) x 128 threads (e)
__global__ void prepWc_kernel(const float* __restrict__ Wih, const float* __restrict__ Wv) {
    __shared__ float row[128];
    int j = blockIdx.x, e = threadIdx.x;
    row[e] = Wih[j * 128 + e];
    __syncthreads();
    float s = 0.0f;
    #pragma unroll 8
    for (int d = 0; d < 128; d++) s += row[d] * Wv[d * 128 + e];
    g_WcT[e * 384 + j] = s;
}

// ---------------- prepMT: MT[e][d] = sum_j Wk[j][d] Wq[j][e] ------------
// grid 128 blocks (e) x 128 threads (d)
__global__ void prepMT_kernel(const float* __restrict__ Wq, const float* __restrict__ Wk) {
    int e = blockIdx.x, d = threadIdx.x;
    float s = 0.0f;
    #pragma unroll 8
    for (int j = 0; j < 128; j++) s += Wk[j * 128 + d] * Wq[j * 128 + e];
    g_MT[e * 128 + d] = s;
}

// ---------------- init: slots broadcast + first qt/qb -------------------
__global__ void init_kernel(const float* __restrict__ slots_init,
                            const float* __restrict__ g_sl, const float* __restrict__ be_sl) {
    __shared__ float lnv[Dc];
    __shared__ float red[4];
    const int t = threadIdx.x;
    const int bs = blockIdx.x;           // b*8 + s
    const int s = bs & 7;
    float v = slots_init[s * Dc + t];
    g_slots[bs * Dc + t] = v;
    float m = blocksum128(v, red) * (1.0f / 128.0f);
    float dx = v - m;
    float var = blocksum128(dx * dx, red) * (1.0f / 128.0f);
    float l = dx * rsqrtf(var + 1e-5f) * g_sl[t] + be_sl[t];
    lnv[t] = l;
    __syncthreads();
    float qa = g_qtb[t];
    #pragma unroll 4
    for (int e = 0; e < 128; e++) qa += g_MT[e * 128 + t] * lnv[e];
    g_qt[bs * Dc + t] = qa;
    float qb = blocksum128(g_qbv[t] * lnv[t], red);
    if (t == 0) g_qb[bs] = qb + g_qbb[0];
}

// ---------------- stepB: LN(x), dots, softmax, ya/ra partials -----------
// grid (16 chunks of 64 tokens, 16 batches), 256 threads
#define XST 132
#define ASTB 65
__global__ void __launch_bounds__(256) stepB_kernel(
        const float* __restrict__ x, int f, int emit, float* __restrict__ out_attn,
        const float* __restrict__ g_in, const float* __restrict__ be_in) {
    __shared__ float xs[CHTOK * XST];    // LN'd x
    __shared__ float qts[Sc * XST];
    __shared__ float as[Sc * ASTB];
    __shared__ float qbs[Sc];

    const int t = threadIdx.x;
    const int lane = t & 31, w = t >> 5;
    const int chunk = blockIdx.x;
    const int b = blockIdx.y;
    const int bf = b * NFc + f;
    const float* xg = x + ((size_t)bf * Nc + (size_t)chunk * CHTOK) * Dc;

    // LN: 8 rows per warp
    float4 gg = ((const float4*)g_in)[lane];
    float4 bb = ((const float4*)be_in)[lane];
    #pragma unroll
    for (int r = w; r < CHTOK; r += 8) {
        float4 v = ((const float4*)(xg + r * Dc))[lane];
        float s = v.x + v.y + v.z + v.w;
        #pragma unroll
        for (int o = 16; o; o >>= 1) s += __shfl_xor_sync(0xffffffffu, s, o);
        float m = s * (1.0f / 128.0f);
        float d0 = v.x - m, d1 = v.y - m, d2 = v.z - m, d3 = v.w - m;
        float ss = d0*d0 + d1*d1 + d2*d2 + d3*d3;
        #pragma unroll
        for (int o = 16; o; o >>= 1) ss += __shfl_xor_sync(0xffffffffu, ss, o);
        float inv = rsqrtf(ss * (1.0f / 128.0f) + 1e-5f);
        float* xr = xs + r * XST + lane * 4;
        xr[0] = d0 * inv * gg.x + bb.x;
        xr[1] = d1 * inv * gg.y + bb.y;
        xr[2] = d2 * inv * gg.z + bb.z;
        xr[3] = d3 * inv * gg.w + bb.w;
    }
    // qt, qb
    {
        int s = t >> 5, dq = (t & 31) * 4;
        *(float4*)(qts + s * XST + dq) = *(const float4*)(g_qt + (b * Sc + s) * Dc + dq);
    }
    if (t < 8) qbs[t] = g_qb[b * Sc + t];
    __syncthreads();

    // dots for tokens tt0, tt0+32, slot s
    const int tt0 = t >> 3;
    const int s = t & 7;
    float dot0 = 0.0f, dot1 = 0.0f;
    const float* qrow = qts + s * XST;
    const float* xrow0 = xs + tt0 * XST;
    const float* xrow1 = xrow0 + 32 * XST;
    #pragma unroll 8
    for (int j = 0; j < 32; j++) {
        float4 q4 = *(const float4*)(qrow + j * 4);
        float4 x0 = *(const float4*)(xrow0 + j * 4);
        float4 x1 = *(const float4*)(xrow1 + j * 4);
        dot0 += q4.x*x0.x + q4.y*x0.y + q4.z*x0.z + q4.w*x0.w;
        dot1 += q4.x*x1.x + q4.y*x1.y + q4.z*x1.z + q4.w*x1.w;
    }
    float qbv = qbs[s];
    dot0 = (dot0 + qbv) * SCALEc;
    dot1 = (dot1 + qbv) * SCALEc;
    float mx0 = dot0, mx1 = dot1;
    #pragma unroll
    for (int o = 4; o; o >>= 1) {
        mx0 = fmaxf(mx0, __shfl_xor_sync(0xffffffffu, mx0, o));
        mx1 = fmaxf(mx1, __shfl_xor_sync(0xffffffffu, mx1, o));
    }
    float e0 = expf(dot0 - mx0), e1 = expf(dot1 - mx1);
    float s0 = e0, s1 = e1;
    #pragma unroll
    for (int o = 4; o; o >>= 1) {
        s0 += __shfl_xor_sync(0xffffffffu, s0, o);
        s1 += __shfl_xor_sync(0xffffffffu, s1, o);
    }
    float a0 = e0 / s0 + EPSc;
    float a1 = e1 / s1 + EPSc;
    as[s * ASTB + tt0] = a0;
    as[s * ASTB + tt0 + 32] = a1;
    __syncthreads();

    // coalesced attn emit
    if (emit) {
        float* oa = out_attn + (size_t)bf * Sc * Nc + chunk * CHTOK;
        #pragma unroll
        for (int i = 0; i < 2; i++) {
            int idx = t + i * 256;
            int s3 = idx >> 6, n3 = idx & 63;
            oa[(size_t)s3 * Nc + n3] = as[s3 * ASTB + n3];
        }
    }

    // rowsum partials: warp w -> slot w
    {
        float rs = as[w * ASTB + lane] + as[w * ASTB + lane + 32];
        #pragma unroll
        for (int o = 16; o; o >>= 1) rs += __shfl_xor_sync(0xffffffffu, rs, o);
        if (lane == 0) g_rspart[chunk * BSc + b * Sc + w] = rs;
    }

    // ya partials: warp w = slot w; lane owns d-quad
    {
        float4 up = make_float4(0.f, 0.f, 0.f, 0.f);
        const float* arow = as + w * ASTB;
        #pragma unroll 8
        for (int n = 0; n < CHTOK; n++) {
            float a = arow[n];
            float4 v4 = *(const float4*)(xs + n * XST + lane * 4);
            up.x += a * v4.x; up.y += a * v4.y;
            up.z += a * v4.z; up.w += a * v4.w;
        }
        *(float4*)(g_Yapart + (size_t)(chunk * BSc + b * Sc + w) * Dc + lane * 4) = up;
    }
}

// ---------------- stepC: gates from ya, GRU, FF, next qt/qb -------------
// grid 128 blocks (one per b*8+s), 384 threads
__global__ void __launch_bounds__(384) stepC_kernel(int f, int emit, float* __restrict__ out_slots,
                             const float* __restrict__ bih, const float* __restrict__ bhh,
                             const float* __restrict__ g_ff, const float* __restrict__ be_ff,
                             const float* __restrict__ b1, const float* __restrict__ b2,
                             const float* __restrict__ g_sl, const float* __restrict__ be_sl) {
    __shared__ float yn[Dc], hs[Dc], hgs[Dc], ffs[Dc], hid[Dc], ln2s[Dc];
    __shared__ float sgA[384], sgB[384], sgA2[384], sgB2[384];
    __shared__ float fpart[8][Dc];
    __shared__ float upp[8][Dc];
    __shared__ float rsp[16];
    __shared__ float red[12];

    const int t = threadIdx.x;
    const int bs = blockIdx.x;

    // phase A: reduce ya partials, normalize by rowsum
    if (t < 256) {
        int cg = t >> 5;
        int dq = (t & 31) * 4;
        float4 ua = *(const float4*)(g_Yapart + (size_t)(cg * BSc + bs) * Dc + dq);
        float4 ub = *(const float4*)(g_Yapart + (size_t)((cg + 8) * BSc + bs) * Dc + dq);
        ua.x += ub.x; ua.y += ub.y; ua.z += ub.z; ua.w += ub.w;
        *(float4*)(&upp[cg][dq]) = ua;
    }
    if (t < 16) rsp[t] = g_rspart[t * BSc + bs];
    __syncthreads();
    if (t < 128) {
        float ysum = 0.0f;
        #pragma unroll
        for (int c = 0; c < 8; c++) ysum += upp[c][t];
        float rsum = 0.0f;
        #pragma unroll
        for (int c = 0; c < 16; c++) rsum += rsp[c];
        yn[t] = ysum / rsum;             // ya / ra  (so u = Wv yn + bv)
        hs[t] = g_slots[bs * Dc + t];
    }
    __syncthreads();

    // phase B: gate GEMVs: gi = Wc yn (+bc+bih later), gh = Whh h (+bhh)
    {
        int grp = t / 96;               // 0: gi e<64, 1: gh e<64, 2: gi e>=64, 3: gh e>=64
        int q = t - grp * 96;
        const float* W = (grp & 1) ? g_WhhT : g_WcT;
        const float* xv = (grp & 1) ? hs : yn;
        int d0 = (grp >> 1) * 64;
        float4 acc = make_float4(0.f, 0.f, 0.f, 0.f);
        #pragma unroll 16
        for (int i = 0; i < 64; i++) {
            int d = d0 + i;
            float4 w4 = *(const float4*)(W + d * 384 + q * 4);
            float xd = xv[d];
            acc.x += xd * w4.x; acc.y += xd * w4.y;
            acc.z += xd * w4.z; acc.w += xd * w4.w;
        }
        float* dst = (grp == 0) ? sgA : (grp == 1) ? sgB : (grp == 2) ? sgA2 : sgB2;
        *(float4*)(dst + q * 4) = acc;
    }
    __syncthreads();

    // phase C: gates + GRU + LN for FF
    float hg = 0.0f;
    if (t < 128) {
        float gi_r = sgA[t]       + sgA2[t]       + g_bc[t]       + bih[t];
        float gh_r = sgB[t]       + sgB2[t]       + bhh[t];
        float gi_z = sgA[128 + t] + sgA2[128 + t] + g_bc[128 + t] + bih[128 + t];
        float gh_z = sgB[128 + t] + sgB2[128 + t] + bhh[128 + t];
        float gi_n = sgA[256 + t] + sgA2[256 + t] + g_bc[256 + t] + bih[256 + t];
        float gh_n = sgB[256 + t] + sgB2[256 + t] + bhh[256 + t];
        float r = sigmoidf_(gi_r + gh_r);
        float z = sigmoidf_(gi_z + gh_z);
        float nn = tanhf(gi_n + r * gh_n);
        hg = (1.0f - z) * nn + z * hs[t];
        hgs[t] = hg;
    }
    {
        float v = (t < 128) ? hg : 0.0f;
        float m = blocksum384(v, red) * (1.0f / 128.0f);
        float dx = (t < 128) ? (hg - m) : 0.0f;
        float var = blocksum384(dx * dx, red) * (1.0f / 128.0f);
        if (t < 128) ffs[t] = dx * rsqrtf(var + 1e-5f) * g_ff[t] + be_ff[t];
    }
    __syncthreads();

    // phase D: FF1
    if (t < 256) {
        int q = t & 31, p = t >> 5;
        float4 acc = make_float4(0.f, 0.f, 0.f, 0.f);
        #pragma unroll
        for (int i = 0; i < 16; i++) {
            int d = p * 16 + i;
            float4 w4 = *(const float4*)(g_W1T + d * Dc + q * 4);
            float xd = ffs[d];
            acc.x += xd * w4.x; acc.y += xd * w4.y;
            acc.z += xd * w4.z; acc.w += xd * w4.w;
        }
        *(float4*)(&fpart[p][q * 4]) = acc;
    }
    __syncthreads();
    if (t < 128) {
        float sum = b1[t];
        #pragma unroll
        for (int p = 0; p < 8; p++) sum += fpart[p][t];
        hid[t] = fmaxf(sum, 0.0f);
    }
    __syncthreads();

    // phase E: FF2
    if (t < 256) {
        int q = t & 31, p = t >> 5;
        float4 acc = make_float4(0.f, 0.f, 0.f, 0.f);
        #pragma unroll
        for (int i = 0; i < 16; i++) {
            int d = p * 16 + i;
            float4 w4 = *(const float4*)(g_W2T + d * Dc + q * 4);
            float xd = hid[d];
            acc.x += xd * w4.x; acc.y += xd * w4.y;
            acc.z += xd * w4.z; acc.w += xd * w4.w;
        }
        *(float4*)(&fpart[p][q * 4]) = acc;
    }
    __syncthreads();
    float snew = 0.0f;
    if (t < 128) {
        float sum = b2[t];
        #pragma unroll
        for (int p = 0; p < 8; p++) sum += fpart[p][t];
        snew = hgs[t] + sum;
        g_slots[bs * Dc + t] = snew;
        if (emit) {
            int b = bs >> 3, s = bs & 7;
            out_slots[(((size_t)b * NFc + f) * Sc + s) * Dc + t] = snew;
        }
    }

    // phase F: LN(snew; g_sl) -> qt = MT ln + qtb, qb = qbv.ln + qbb
    {
        float v = (t < 128) ? snew : 0.0f;
        float m = blocksum384(v, red) * (1.0f / 128.0f);
        float dx = (t < 128) ? (snew - m) : 0.0f;
        float var = blocksum384(dx * dx, red) * (1.0f / 128.0f);
        if (t < 128) ln2s[t] = dx * rsqrtf(var + 1e-5f) * g_sl[t] + be_sl[t];
    }
    __syncthreads();
    {
        float qv = (t < 128) ? (g_qbv[t] * ln2s[t]) : 0.0f;
        float qb = blocksum384(qv, red);
        if (t == 0) g_qb[bs] = qb + g_qbb[0];
    }
    if (t < 256) {
        int q = t & 31, p = t >> 5;
        float4 acc = make_float4(0.f, 0.f, 0.f, 0.f);
        #pragma unroll
        for (int i = 0; i < 16; i++) {
            int e = p * 16 + i;
            float4 w4 = *(const float4*)(g_MT + e * 128 + q * 4);
            float xd = ln2s[e];
            acc.x += xd * w4.x; acc.y += xd * w4.y;
            acc.z += xd * w4.z; acc.w += xd * w4.w;
        }
        *(float4*)(&fpart[p][q * 4]) = acc;
    }
    __syncthreads();
    if (t < 128) {
        float sum = g_qtb[t];
        #pragma unroll
        for (int p = 0; p < 8; p++) sum += fpart[p][t];
        g_qt[bs * Dc + t] = sum;
    }
}

// ---------------- launch ----------------
extern "C" void kernel_launch(void* const* d_in, const int* in_sizes, int n_in,
                              void* d_out, int out_size) {
    const float* inputs     = (const float*)d_in[0];
    const float* slots_init = (const float*)d_in[1];
    const float* Wq  = (const float*)d_in[2];
    const float* bq  = (const float*)d_in[3];
    const float* Wk  = (const float*)d_in[4];
    const float* bk  = (const float*)d_in[5];
    const float* Wv  = (const float*)d_in[6];
    const float* bv  = (const float*)d_in[7];
    const float* W1  = (const float*)d_in[8];
    const float* b1  = (const float*)d_in[9];
    const float* W2  = (const float*)d_in[10];
    const float* b2  = (const float*)d_in[11];
    const float* Wih = (const float*)d_in[12];
    const float* Whh = (const float*)d_in[13];
    const float* bih = (const float*)d_in[14];
    const float* bhh = (const float*)d_in[15];
    const float* g_in  = (const float*)d_in[16];
    const float* be_in = (const float*)d_in[17];
    const float* g_sl  = (const float*)d_in[18];
    const float* be_sl = (const float*)d_in[19];
    const float* g_ff  = (const float*)d_in[20];
    const float* be_ff = (const float*)d_in[21];

    float* out = (float*)d_out;
    float* out_slots = out;                                 // [B,NF,S,D]
    float* out_attn  = out + (size_t)Bc * NFc * Sc * Dc;    // [B,NF,S,N]

    prepT_kernel<<<193, 256>>>(Wq, bq, Wk, bk, W1, W2, Wih, Whh, bv);
    prepWc_kernel<<<384, 128>>>(Wih, Wv);
    prepMT_kernel<<<128, 128>>>(Wq, Wk);
    init_kernel<<<BSc, Dc>>>(slots_init, g_sl, be_sl);

    for (int step = 0; step < NFc + 1; step++) {
        int f = (step == 0) ? 0 : step - 1;
        int emit = (step > 0) ? 1 : 0;
        stepB_kernel<<<dim3(NCHUNK, Bc), 256>>>(inputs, f, emit, out_attn, g_in, be_in);
        stepC_kernel<<<BSc, 384>>>(f, emit, out_slots,
                                   bih, bhh, g_ff, be_ff, b1, b2, g_sl, be_sl);
    }
}